// round 1
// baseline (speedup 1.0000x reference)
#include <cuda_runtime.h>
#include <math.h>

#define TT 2048
#define HID 4608
#define NH 36
#define NKV 4
#define HD 128
#define QKVD 5632   // NH*HD + 2*NKV*HD = 4608 + 1024
#define GROUP 9     // NH / NKV
#define ATT_SCALE 0.08838834764831843f  // 1/sqrt(128)
#define NEGINF (-1e30f)

// Scratch (no cudaMalloc allowed)
__device__ float g_qkv[TT * QKVD];        // 46 MB
__device__ float g_attn[TT * NH * HD];    // 37.7 MB

// ---------------------------------------------------------------------------
// SGEMM:  C[m,n] = sum_k A[m,k] * B[n,k] + bias[n]
// A: [M,K] row-major, B: [N,K] row-major (i.e. C = A @ B^T + bias)
// 128x128 tile, BK=16, 256 threads, 8x8 microtile.
// Requires M%128==0, N%128==0, K%16==0 (true for all calls here).
// ---------------------------------------------------------------------------
__global__ __launch_bounds__(256) void sgemm_nt(const float* __restrict__ A,
                                                const float* __restrict__ B,
                                                const float* __restrict__ bias,
                                                float* __restrict__ C,
                                                int M, int N, int K)
{
    __shared__ float As[16][132];
    __shared__ float Bs[16][132];

    const int tid = threadIdx.x;
    const int bm = blockIdx.y * 128;
    const int bn = blockIdx.x * 128;
    const int ty = tid >> 4;   // 0..15
    const int tx = tid & 15;   // 0..15

    const int rowL = tid >> 2;   // 0..63 (load row)
    const int cvec = tid & 3;    // float4 column within BK=16

    float acc[8][8];
#pragma unroll
    for (int i = 0; i < 8; i++)
#pragma unroll
        for (int j = 0; j < 8; j++) acc[i][j] = 0.0f;

    for (int k0 = 0; k0 < K; k0 += 16) {
        // global loads (registers)
        float4 a0 = *(const float4*)(A + (size_t)(bm + rowL) * K + k0 + cvec * 4);
        float4 a1 = *(const float4*)(A + (size_t)(bm + rowL + 64) * K + k0 + cvec * 4);
        float4 b0 = *(const float4*)(B + (size_t)(bn + rowL) * K + k0 + cvec * 4);
        float4 b1 = *(const float4*)(B + (size_t)(bn + rowL + 64) * K + k0 + cvec * 4);

        __syncthreads();  // previous tile fully consumed

        // transposed stores: As[kk][row]
        As[cvec * 4 + 0][rowL] = a0.x;
        As[cvec * 4 + 1][rowL] = a0.y;
        As[cvec * 4 + 2][rowL] = a0.z;
        As[cvec * 4 + 3][rowL] = a0.w;
        As[cvec * 4 + 0][rowL + 64] = a1.x;
        As[cvec * 4 + 1][rowL + 64] = a1.y;
        As[cvec * 4 + 2][rowL + 64] = a1.z;
        As[cvec * 4 + 3][rowL + 64] = a1.w;

        Bs[cvec * 4 + 0][rowL] = b0.x;
        Bs[cvec * 4 + 1][rowL] = b0.y;
        Bs[cvec * 4 + 2][rowL] = b0.z;
        Bs[cvec * 4 + 3][rowL] = b0.w;
        Bs[cvec * 4 + 0][rowL + 64] = b1.x;
        Bs[cvec * 4 + 1][rowL + 64] = b1.y;
        Bs[cvec * 4 + 2][rowL + 64] = b1.z;
        Bs[cvec * 4 + 3][rowL + 64] = b1.w;

        __syncthreads();

#pragma unroll
        for (int kk = 0; kk < 16; kk++) {
            float4 av0 = *(const float4*)&As[kk][ty * 8];
            float4 av1 = *(const float4*)&As[kk][ty * 8 + 4];
            float4 bv0 = *(const float4*)&Bs[kk][tx * 8];
            float4 bv1 = *(const float4*)&Bs[kk][tx * 8 + 4];
            float a[8] = {av0.x, av0.y, av0.z, av0.w, av1.x, av1.y, av1.z, av1.w};
            float b[8] = {bv0.x, bv0.y, bv0.z, bv0.w, bv1.x, bv1.y, bv1.z, bv1.w};
#pragma unroll
            for (int i = 0; i < 8; i++)
#pragma unroll
                for (int j = 0; j < 8; j++)
                    acc[i][j] = fmaf(a[i], b[j], acc[i][j]);
        }
    }

    // epilogue
#pragma unroll
    for (int i = 0; i < 8; i++) {
        int r = bm + ty * 8 + i;
#pragma unroll
        for (int j = 0; j < 8; j++) {
            int c = bn + tx * 8 + j;
            C[(size_t)r * N + c] = acc[i][j] + bias[c];
        }
    }
}

// ---------------------------------------------------------------------------
// NeoX RoPE, in-place over q and k regions of g_qkv.
// grid: (NH+NKV, TT), block: 64 (one thread per rotation pair)
// ---------------------------------------------------------------------------
__global__ __launch_bounds__(64) void rope_kernel(float* __restrict__ qkv,
                                                  const int* __restrict__ positions)
{
    const int d = threadIdx.x;          // 0..63
    const int hh = blockIdx.x;          // 0..39
    const int t = blockIdx.y;

    float* base;
    if (hh < NH) base = qkv + (size_t)t * QKVD + hh * HD;
    else         base = qkv + (size_t)t * QKVD + NH * HD + (hh - NH) * HD;

    const float pos = (float)positions[t];
    // inv_freq = theta^(-d/64) = exp(-ln(1e5) * d / 64)
    const float inv_freq = expf(-11.512925464970229f * ((float)d / 64.0f));
    const float ang = pos * inv_freq;
    float s, c;
    sincosf(ang, &s, &c);

    const float x1 = base[d];
    const float x2 = base[d + 64];
    base[d]      = x1 * c - x2 * s;
    base[d + 64] = x2 * c + x1 * s;
}

// ---------------------------------------------------------------------------
// Windowed causal flash attention.
// grid: (TT/64, NH), 256 threads. BM=BN=64, D=128.
// Thread layout: tr=tid/16 (4 query rows), tc=tid%16.
//   S microtile: 4x4 (rows 4tr.., cols 4tc..)
//   O microtile: 4 rows x 8 head-dims (cols tc*8..)
// ---------------------------------------------------------------------------
#define QS_STRIDE 129
#define KS_STRIDE 129
#define VS_STRIDE 128
#define PS_STRIDE 65
#define SMEM_ATTN ((64 * QS_STRIDE + 64 * KS_STRIDE + 64 * VS_STRIDE + 64 * PS_STRIDE) * 4)

__global__ __launch_bounds__(256) void attn_kernel(const float* __restrict__ qkv,
                                                   float* __restrict__ attnOut,
                                                   const int* __restrict__ winp)
{
    extern __shared__ float sm[];
    float* Qs = sm;                      // [64][129]
    float* Ks = Qs + 64 * QS_STRIDE;     // [64][129]
    float* Vs = Ks + 64 * KS_STRIDE;     // [64][128]
    float* Ps = Vs + 64 * VS_STRIDE;     // [64][65]

    const int tid = threadIdx.x;
    const int tr = tid >> 4;
    const int tc = tid & 15;
    const int h = blockIdx.y;
    const int qt0 = blockIdx.x * 64;
    const int kvh = h / GROUP;
    const int window = *winp;

    // Load Q tile: 64 rows x 128 cols
    for (int idx = tid; idx < 64 * 32; idx += 256) {
        int row = idx >> 5;
        int c4 = idx & 31;
        float4 v = *(const float4*)(qkv + (size_t)(qt0 + row) * QKVD + h * HD + c4 * 4);
        float* dst = Qs + row * QS_STRIDE + c4 * 4;
        dst[0] = v.x; dst[1] = v.y; dst[2] = v.z; dst[3] = v.w;
    }

    float m[4], l[4], O[4][8];
#pragma unroll
    for (int i = 0; i < 4; i++) {
        m[i] = NEGINF;
        l[i] = 0.0f;
#pragma unroll
        for (int d = 0; d < 8; d++) O[i][d] = 0.0f;
    }

    int sBegin = qt0 - window + 1;
    if (sBegin < 0) sBegin = 0;
    sBegin &= ~63;
    const int sEnd = qt0 + 63;

    const size_t kOff = (size_t)NH * HD + (size_t)kvh * HD;
    const size_t vOff = (size_t)NH * HD + (size_t)NKV * HD + (size_t)kvh * HD;

    for (int s0 = sBegin; s0 <= sEnd; s0 += 64) {
        __syncthreads();  // previous iteration done with Ks/Vs/Ps; Q store visible

        // Load K and V tiles
        for (int idx = tid; idx < 64 * 32; idx += 256) {
            int row = idx >> 5;
            int c4 = idx & 31;
            float4 kv4 = *(const float4*)(qkv + (size_t)(s0 + row) * QKVD + kOff + c4 * 4);
            float* kd = Ks + row * KS_STRIDE + c4 * 4;
            kd[0] = kv4.x; kd[1] = kv4.y; kd[2] = kv4.z; kd[3] = kv4.w;
            float4 vv4 = *(const float4*)(qkv + (size_t)(s0 + row) * QKVD + vOff + c4 * 4);
            *(float4*)(Vs + row * VS_STRIDE + c4 * 4) = vv4;
        }
        __syncthreads();

        // S = Q @ K^T (4x4 microtile)
        float S[4][4];
#pragma unroll
        for (int i = 0; i < 4; i++)
#pragma unroll
            for (int j = 0; j < 4; j++) S[i][j] = 0.0f;

#pragma unroll 4
        for (int kk = 0; kk < 128; kk++) {
            float a[4], b[4];
#pragma unroll
            for (int i = 0; i < 4; i++) a[i] = Qs[(4 * tr + i) * QS_STRIDE + kk];
#pragma unroll
            for (int j = 0; j < 4; j++) b[j] = Ks[(4 * tc + j) * KS_STRIDE + kk];
#pragma unroll
            for (int i = 0; i < 4; i++)
#pragma unroll
                for (int j = 0; j < 4; j++)
                    S[i][j] = fmaf(a[i], b[j], S[i][j]);
        }

        // scale + window mask
#pragma unroll
        for (int i = 0; i < 4; i++) {
            int tq = qt0 + 4 * tr + i;
#pragma unroll
            for (int j = 0; j < 4; j++) {
                int sk = s0 + 4 * tc + j;
                bool ok = (sk <= tq) && (sk > tq - window);
                S[i][j] = ok ? S[i][j] * ATT_SCALE : NEGINF;
            }
        }

        // online softmax per row (16 lanes per row, width-16 shfl)
#pragma unroll
        for (int i = 0; i < 4; i++) {
            float tmax = fmaxf(fmaxf(S[i][0], S[i][1]), fmaxf(S[i][2], S[i][3]));
#pragma unroll
            for (int off = 8; off >= 1; off >>= 1)
                tmax = fmaxf(tmax, __shfl_xor_sync(0xffffffffu, tmax, off, 16));

            float mn = fmaxf(m[i], tmax);
            float corr = expf(m[i] - mn);
            m[i] = mn;

            float rsum = 0.0f;
#pragma unroll
            for (int j = 0; j < 4; j++) {
                S[i][j] = expf(S[i][j] - mn);
                rsum += S[i][j];
            }
#pragma unroll
            for (int off = 8; off >= 1; off >>= 1)
                rsum += __shfl_xor_sync(0xffffffffu, rsum, off, 16);

            l[i] = l[i] * corr + rsum;
#pragma unroll
            for (int d = 0; d < 8; d++) O[i][d] *= corr;

            // stash P
#pragma unroll
            for (int j = 0; j < 4; j++)
                Ps[(4 * tr + i) * PS_STRIDE + 4 * tc + j] = S[i][j];
        }
        __syncthreads();

        // O += P @ V  (rows 4tr.., dims tc*8..)
#pragma unroll 4
        for (int kk = 0; kk < 64; kk++) {
            float a[4];
#pragma unroll
            for (int i = 0; i < 4; i++) a[i] = Ps[(4 * tr + i) * PS_STRIDE + kk];
            float4 v0 = *(const float4*)(Vs + kk * VS_STRIDE + tc * 8);
            float4 v1 = *(const float4*)(Vs + kk * VS_STRIDE + tc * 8 + 4);
            float b[8] = {v0.x, v0.y, v0.z, v0.w, v1.x, v1.y, v1.z, v1.w};
#pragma unroll
            for (int i = 0; i < 4; i++)
#pragma unroll
                for (int d = 0; d < 8; d++)
                    O[i][d] = fmaf(a[i], b[d], O[i][d]);
        }
    }

    // epilogue: normalize and write
#pragma unroll
    for (int i = 0; i < 4; i++) {
        float inv = 1.0f / l[i];
        int row = qt0 + 4 * tr + i;
        float* dst = attnOut + (size_t)row * (NH * HD) + h * HD + tc * 8;
#pragma unroll
        for (int d = 0; d < 8; d++) dst[d] = O[i][d] * inv;
    }
}

// ---------------------------------------------------------------------------
extern "C" void kernel_launch(void* const* d_in, const int* in_sizes, int n_in,
                              void* d_out, int out_size)
{
    const int*   positions = (const int*)d_in[0];
    const float* hidden    = (const float*)d_in[1];
    const float* wqkv      = (const float*)d_in[2];
    const float* bqkv      = (const float*)d_in[3];
    const float* wo        = (const float*)d_in[4];
    const float* bo        = (const float*)d_in[5];
    const int*   window    = (const int*)d_in[6];
    float* out = (float*)d_out;

    float* qkv_ptr;
    float* attn_ptr;
    cudaGetSymbolAddress((void**)&qkv_ptr, g_qkv);
    cudaGetSymbolAddress((void**)&attn_ptr, g_attn);

    // 1. QKV = hidden @ wqkv^T + bqkv
    sgemm_nt<<<dim3(QKVD / 128, TT / 128), 256>>>(hidden, wqkv, bqkv, qkv_ptr,
                                                  TT, QKVD, HID);
    // 2. RoPE on q,k
    rope_kernel<<<dim3(NH + NKV, TT), 64>>>(qkv_ptr, positions);

    // 3. windowed attention
    cudaFuncSetAttribute(attn_kernel, cudaFuncAttributeMaxDynamicSharedMemorySize,
                         SMEM_ATTN);
    attn_kernel<<<dim3(TT / 64, NH), 256, SMEM_ATTN>>>(qkv_ptr, attn_ptr, window);

    // 4. out = attn @ wo^T + bo
    sgemm_nt<<<dim3(HID / 128, TT / 128), 256>>>(attn_ptr, wo, bo, out,
                                                 TT, HID, HID);
}

// round 3
// speedup vs baseline: 1.7437x; 1.7437x over previous
#include <cuda_runtime.h>
#include <cuda_bf16.h>
#include <math.h>
#include <stdint.h>

#define TT 2048
#define HID 4608
#define NH 36
#define NKV 4
#define HD 128
#define QKVD 5632   // NH*HD + 2*NKV*HD
#define GROUP 9     // NH / NKV
#define ATT_SCALE 0.08838834764831843f
#define NEGINF (-1e30f)

// ---------------- scratch (no cudaMalloc allowed) ----------------
__device__ float g_qkv[TT * QKVD];
__device__ float g_attn[TT * NH * HD];
__device__ __nv_bfloat16 g_hid_hi[TT * HID];
__device__ __nv_bfloat16 g_hid_lo[TT * HID];
__device__ __nv_bfloat16 g_wqkv_hi[QKVD * HID];
__device__ __nv_bfloat16 g_wqkv_lo[QKVD * HID];
__device__ __nv_bfloat16 g_wo_hi[HID * HID];
__device__ __nv_bfloat16 g_wo_lo[HID * HID];
__device__ __nv_bfloat16 g_attn_hi[TT * HID];
__device__ __nv_bfloat16 g_attn_lo[TT * HID];

__device__ __forceinline__ uint32_t smem_u32(const void* p) {
    uint32_t a;
    asm("{ .reg .u64 t; cvta.to.shared.u64 t, %1; cvt.u32.u64 %0, t; }" : "=r"(a) : "l"(p));
    return a;
}

// ---------------------------------------------------------------------------
// fp32 -> bf16 hi/lo split
// ---------------------------------------------------------------------------
__global__ __launch_bounds__(256) void split_bf16(const float* __restrict__ x,
                                                  __nv_bfloat16* __restrict__ hi,
                                                  __nv_bfloat16* __restrict__ lo,
                                                  int n4)
{
    int i = blockIdx.x * 256 + threadIdx.x;
    if (i >= n4) return;
    float4 v = ((const float4*)x)[i];
    __nv_bfloat16 h0 = __float2bfloat16(v.x);
    __nv_bfloat16 h1 = __float2bfloat16(v.y);
    __nv_bfloat16 h2 = __float2bfloat16(v.z);
    __nv_bfloat16 h3 = __float2bfloat16(v.w);
    __nv_bfloat16 l0 = __float2bfloat16(v.x - __bfloat162float(h0));
    __nv_bfloat16 l1 = __float2bfloat16(v.y - __bfloat162float(h1));
    __nv_bfloat16 l2 = __float2bfloat16(v.z - __bfloat162float(h2));
    __nv_bfloat16 l3 = __float2bfloat16(v.w - __bfloat162float(h3));
    union { __nv_bfloat16 b[4]; uint2 u; } H, L;
    H.b[0] = h0; H.b[1] = h1; H.b[2] = h2; H.b[3] = h3;
    L.b[0] = l0; L.b[1] = l1; L.b[2] = l2; L.b[3] = l3;
    ((uint2*)hi)[i] = H.u;
    ((uint2*)lo)[i] = L.u;
}

// ---------------------------------------------------------------------------
// bf16x3 GEMM via mma.sync (HMMA):  C[m,n] = sum_k A[m,k]*B[n,k] + bias[n]
// 128x128 CTA tile, BK=32, 8 warps (2x4), each warp 64x32.
// Double-buffered cp.async. Smem rows padded to 80B (conflict-free ldmatrix).
// ---------------------------------------------------------------------------
#define GBM 128
#define GBN 128
#define GBK 32
#define ROWB 80                     // bytes per smem row (32 bf16 + 8 pad)
#define TILE_B (128 * ROWB)         // 10240 per operand tile
#define STAGE_B (4 * TILE_B)        // Ahi, Alo, Bhi, Blo
#define GEMM_SMEM (2 * STAGE_B)     // 81920

__device__ __forceinline__ void ldm_x4(uint32_t* r, uint32_t addr) {
    asm volatile("ldmatrix.sync.aligned.m8n8.x4.shared.b16 {%0,%1,%2,%3}, [%4];"
                 : "=r"(r[0]), "=r"(r[1]), "=r"(r[2]), "=r"(r[3]) : "r"(addr));
}
__device__ __forceinline__ void mma16816(float* d, const uint32_t* a, uint32_t b0, uint32_t b1) {
    asm volatile(
        "mma.sync.aligned.m16n8k16.row.col.f32.bf16.bf16.f32 "
        "{%0,%1,%2,%3}, {%4,%5,%6,%7}, {%8,%9}, {%0,%1,%2,%3};"
        : "+f"(d[0]), "+f"(d[1]), "+f"(d[2]), "+f"(d[3])
        : "r"(a[0]), "r"(a[1]), "r"(a[2]), "r"(a[3]), "r"(b0), "r"(b1));
}

__global__ __launch_bounds__(256, 1) void gemm_mma(
    const __nv_bfloat16* __restrict__ Ahi, const __nv_bfloat16* __restrict__ Alo,
    const __nv_bfloat16* __restrict__ Bhi, const __nv_bfloat16* __restrict__ Blo,
    const float* __restrict__ bias, float* __restrict__ C,
    int M, int N, int K)
{
    extern __shared__ char smem[];
    const uint32_t sb = smem_u32(smem);
    const int tid = threadIdx.x, wid = tid >> 5, lane = tid & 31;
    const int warp_m = wid & 1;          // 2 warps over M
    const int warp_n = wid >> 1;         // 4 warps over N
    const int bm = blockIdx.x * GBM, bn = blockIdx.y * GBN;

    float acc[4][4][4];
#pragma unroll
    for (int i = 0; i < 4; i++)
#pragma unroll
        for (int j = 0; j < 4; j++)
#pragma unroll
            for (int q = 0; q < 4; q++) acc[i][j][q] = 0.0f;

    // cp.async stage loader: 2048 16B chunks, 8 per thread
    auto load_stage = [&](int stg, int k0) {
        uint32_t base = sb + stg * STAGE_B;
#pragma unroll
        for (int i = 0; i < 8; i++) {
            int c = tid + i * 256;
            int tile = c >> 9;          // 0:Ahi 1:Alo 2:Bhi 3:Blo
            int idx = c & 511;
            int row = idx >> 2, ch = idx & 3;
            const __nv_bfloat16* g;
            int grow;
            if (tile < 2) { g = tile ? Alo : Ahi; grow = bm + row; }
            else          { g = (tile == 3) ? Blo : Bhi; grow = bn + row; }
            const char* src = (const char*)(g + (size_t)grow * K + k0) + ch * 16;
            uint32_t dst = base + tile * TILE_B + row * ROWB + ch * 16;
            asm volatile("cp.async.cg.shared.global [%0], [%1], 16;" :: "r"(dst), "l"(src));
        }
        asm volatile("cp.async.commit_group;" ::: "memory");
    };

    const int NKB = K / GBK;
    load_stage(0, 0);

    // per-lane ldmatrix address components
    const int a_row = (lane & 15);
    const int a_kh = lane >> 4;                          // 0/1 -> k0/k8 (x16 B)
    const int b_nrow = (lane & 7) + ((lane >> 4) & 1) * 8;
    const int b_kh = (lane >> 3) & 1;

    for (int kb = 0; kb < NKB; kb++) {
        const int cur = kb & 1;
        asm volatile("cp.async.wait_group 0;" ::: "memory");
        __syncthreads();

        if (kb + 1 < NKB) load_stage(cur ^ 1, (kb + 1) * GBK);

        const uint32_t stage = sb + cur * STAGE_B;
        const uint32_t Ah = stage;
        const uint32_t Al = stage + TILE_B;
        const uint32_t Bh = stage + 2 * TILE_B;
        const uint32_t Bl = stage + 3 * TILE_B;

#pragma unroll
        for (int ks = 0; ks < 2; ks++) {
            uint32_t ah[4][4], al[4][4];
#pragma unroll
            for (int mf = 0; mf < 4; mf++) {
                uint32_t off = (warp_m * 64 + mf * 16 + a_row) * ROWB + ks * 32 + a_kh * 16;
                ldm_x4(ah[mf], Ah + off);
                ldm_x4(al[mf], Al + off);
            }
            uint32_t bh[2][4], bl[2][4];
#pragma unroll
            for (int p = 0; p < 2; p++) {
                uint32_t off = (warp_n * 32 + p * 16 + b_nrow) * ROWB + ks * 32 + b_kh * 16;
                ldm_x4(bh[p], Bh + off);
                ldm_x4(bl[p], Bl + off);
            }
#pragma unroll
            for (int mf = 0; mf < 4; mf++) {
#pragma unroll
                for (int nf = 0; nf < 4; nf++) {
                    const int p = nf >> 1, o = (nf & 1) * 2;
                    mma16816(acc[mf][nf], ah[mf], bh[p][o], bh[p][o + 1]);  // hi*hi
                    mma16816(acc[mf][nf], ah[mf], bl[p][o], bl[p][o + 1]);  // hi*lo
                    mma16816(acc[mf][nf], al[mf], bh[p][o], bh[p][o + 1]);  // lo*hi
                }
            }
        }
        __syncthreads();
    }

    // epilogue
    const int qr = lane >> 2, qc = (lane & 3) * 2;
#pragma unroll
    for (int mf = 0; mf < 4; mf++) {
        int row0 = bm + warp_m * 64 + mf * 16 + qr;
#pragma unroll
        for (int nf = 0; nf < 4; nf++) {
            int col = bn + warp_n * 32 + nf * 8 + qc;
            float2 bv = *(const float2*)(bias + col);
            float2 v0 = { acc[mf][nf][0] + bv.x, acc[mf][nf][1] + bv.y };
            float2 v1 = { acc[mf][nf][2] + bv.x, acc[mf][nf][3] + bv.y };
            *(float2*)(C + (size_t)row0 * N + col) = v0;
            *(float2*)(C + (size_t)(row0 + 8) * N + col) = v1;
        }
    }
}

// ---------------------------------------------------------------------------
// NeoX RoPE
// ---------------------------------------------------------------------------
__global__ __launch_bounds__(64) void rope_kernel(float* __restrict__ qkv,
                                                  const int* __restrict__ positions)
{
    const int d = threadIdx.x;
    const int hh = blockIdx.x;
    const int t = blockIdx.y;

    float* base;
    if (hh < NH) base = qkv + (size_t)t * QKVD + hh * HD;
    else         base = qkv + (size_t)t * QKVD + NH * HD + (hh - NH) * HD;

    const float pos = (float)positions[t];
    const float inv_freq = expf(-11.512925464970229f * ((float)d / 64.0f));
    const float ang = pos * inv_freq;
    float s, c;
    sincosf(ang, &s, &c);

    const float x1 = base[d];
    const float x2 = base[d + 64];
    base[d]      = x1 * c - x2 * s;
    base[d + 64] = x2 * c + x1 * s;
}

// ---------------------------------------------------------------------------
// Windowed causal flash attention (SIMT fp32)
// ---------------------------------------------------------------------------
#define QS_STRIDE 129
#define KS_STRIDE 129
#define VS_STRIDE 128
#define PS_STRIDE 65
#define SMEM_ATTN ((64 * QS_STRIDE + 64 * KS_STRIDE + 64 * VS_STRIDE + 64 * PS_STRIDE) * 4)

__global__ __launch_bounds__(256) void attn_kernel(const float* __restrict__ qkv,
                                                   float* __restrict__ attnOut,
                                                   const int* __restrict__ winp)
{
    extern __shared__ float sm[];
    float* Qs = sm;
    float* Ks = Qs + 64 * QS_STRIDE;
    float* Vs = Ks + 64 * KS_STRIDE;
    float* Ps = Vs + 64 * VS_STRIDE;

    const int tid = threadIdx.x;
    const int tr = tid >> 4;
    const int tc = tid & 15;
    const int h = blockIdx.y;
    const int qt0 = blockIdx.x * 64;
    const int kvh = h / GROUP;
    const int window = *winp;

    for (int idx = tid; idx < 64 * 32; idx += 256) {
        int row = idx >> 5;
        int c4 = idx & 31;
        float4 v = *(const float4*)(qkv + (size_t)(qt0 + row) * QKVD + h * HD + c4 * 4);
        float* dst = Qs + row * QS_STRIDE + c4 * 4;
        dst[0] = v.x; dst[1] = v.y; dst[2] = v.z; dst[3] = v.w;
    }

    float m[4], l[4], O[4][8];
#pragma unroll
    for (int i = 0; i < 4; i++) {
        m[i] = NEGINF;
        l[i] = 0.0f;
#pragma unroll
        for (int d = 0; d < 8; d++) O[i][d] = 0.0f;
    }

    int sBegin = qt0 - window + 1;
    if (sBegin < 0) sBegin = 0;
    sBegin &= ~63;
    const int sEnd = qt0 + 63;

    const size_t kOff = (size_t)NH * HD + (size_t)kvh * HD;
    const size_t vOff = (size_t)NH * HD + (size_t)NKV * HD + (size_t)kvh * HD;

    for (int s0 = sBegin; s0 <= sEnd; s0 += 64) {
        __syncthreads();

        for (int idx = tid; idx < 64 * 32; idx += 256) {
            int row = idx >> 5;
            int c4 = idx & 31;
            float4 kv4 = *(const float4*)(qkv + (size_t)(s0 + row) * QKVD + kOff + c4 * 4);
            float* kd = Ks + row * KS_STRIDE + c4 * 4;
            kd[0] = kv4.x; kd[1] = kv4.y; kd[2] = kv4.z; kd[3] = kv4.w;
            float4 vv4 = *(const float4*)(qkv + (size_t)(s0 + row) * QKVD + vOff + c4 * 4);
            *(float4*)(Vs + row * VS_STRIDE + c4 * 4) = vv4;
        }
        __syncthreads();

        float S[4][4];
#pragma unroll
        for (int i = 0; i < 4; i++)
#pragma unroll
            for (int j = 0; j < 4; j++) S[i][j] = 0.0f;

#pragma unroll 4
        for (int kk = 0; kk < 128; kk++) {
            float a[4], b[4];
#pragma unroll
            for (int i = 0; i < 4; i++) a[i] = Qs[(4 * tr + i) * QS_STRIDE + kk];
#pragma unroll
            for (int j = 0; j < 4; j++) b[j] = Ks[(4 * tc + j) * KS_STRIDE + kk];
#pragma unroll
            for (int i = 0; i < 4; i++)
#pragma unroll
                for (int j = 0; j < 4; j++)
                    S[i][j] = fmaf(a[i], b[j], S[i][j]);
        }

#pragma unroll
        for (int i = 0; i < 4; i++) {
            int tq = qt0 + 4 * tr + i;
#pragma unroll
            for (int j = 0; j < 4; j++) {
                int sk = s0 + 4 * tc + j;
                bool ok = (sk <= tq) && (sk > tq - window);
                S[i][j] = ok ? S[i][j] * ATT_SCALE : NEGINF;
            }
        }

#pragma unroll
        for (int i = 0; i < 4; i++) {
            float tmax = fmaxf(fmaxf(S[i][0], S[i][1]), fmaxf(S[i][2], S[i][3]));
#pragma unroll
            for (int off = 8; off >= 1; off >>= 1)
                tmax = fmaxf(tmax, __shfl_xor_sync(0xffffffffu, tmax, off, 16));

            float mn = fmaxf(m[i], tmax);
            float corr = expf(m[i] - mn);
            m[i] = mn;

            float rsum = 0.0f;
#pragma unroll
            for (int j = 0; j < 4; j++) {
                S[i][j] = expf(S[i][j] - mn);
                rsum += S[i][j];
            }
#pragma unroll
            for (int off = 8; off >= 1; off >>= 1)
                rsum += __shfl_xor_sync(0xffffffffu, rsum, off, 16);

            l[i] = l[i] * corr + rsum;
#pragma unroll
            for (int d = 0; d < 8; d++) O[i][d] *= corr;

#pragma unroll
            for (int j = 0; j < 4; j++)
                Ps[(4 * tr + i) * PS_STRIDE + 4 * tc + j] = S[i][j];
        }
        __syncthreads();

#pragma unroll 4
        for (int kk = 0; kk < 64; kk++) {
            float a[4];
#pragma unroll
            for (int i = 0; i < 4; i++) a[i] = Ps[(4 * tr + i) * PS_STRIDE + kk];
            float4 v0 = *(const float4*)(Vs + kk * VS_STRIDE + tc * 8);
            float4 v1 = *(const float4*)(Vs + kk * VS_STRIDE + tc * 8 + 4);
            float b[8] = {v0.x, v0.y, v0.z, v0.w, v1.x, v1.y, v1.z, v1.w};
#pragma unroll
            for (int i = 0; i < 4; i++)
#pragma unroll
                for (int d = 0; d < 8; d++)
                    O[i][d] = fmaf(a[i], b[d], O[i][d]);
        }
    }

#pragma unroll
    for (int i = 0; i < 4; i++) {
        float inv = 1.0f / l[i];
        int row = qt0 + 4 * tr + i;
        float* dst = attnOut + (size_t)row * (NH * HD) + h * HD + tc * 8;
#pragma unroll
        for (int d = 0; d < 8; d++) dst[d] = O[i][d] * inv;
    }
}

// ---------------------------------------------------------------------------
extern "C" void kernel_launch(void* const* d_in, const int* in_sizes, int n_in,
                              void* d_out, int out_size)
{
    const int*   positions = (const int*)d_in[0];
    const float* hidden    = (const float*)d_in[1];
    const float* wqkv      = (const float*)d_in[2];
    const float* bqkv      = (const float*)d_in[3];
    const float* wo        = (const float*)d_in[4];
    const float* bo        = (const float*)d_in[5];
    const int*   window    = (const int*)d_in[6];
    float* out = (float*)d_out;

    float *qkv_ptr, *attn_ptr;
    __nv_bfloat16 *hid_hi, *hid_lo, *wqkv_hi, *wqkv_lo, *wo_hi, *wo_lo, *attn_hi, *attn_lo;
    cudaGetSymbolAddress((void**)&qkv_ptr,  g_qkv);
    cudaGetSymbolAddress((void**)&attn_ptr, g_attn);
    cudaGetSymbolAddress((void**)&hid_hi,   g_hid_hi);
    cudaGetSymbolAddress((void**)&hid_lo,   g_hid_lo);
    cudaGetSymbolAddress((void**)&wqkv_hi,  g_wqkv_hi);
    cudaGetSymbolAddress((void**)&wqkv_lo,  g_wqkv_lo);
    cudaGetSymbolAddress((void**)&wo_hi,    g_wo_hi);
    cudaGetSymbolAddress((void**)&wo_lo,    g_wo_lo);
    cudaGetSymbolAddress((void**)&attn_hi,  g_attn_hi);
    cudaGetSymbolAddress((void**)&attn_lo,  g_attn_lo);

    cudaFuncSetAttribute(gemm_mma, cudaFuncAttributeMaxDynamicSharedMemorySize, GEMM_SMEM);
    cudaFuncSetAttribute(attn_kernel, cudaFuncAttributeMaxDynamicSharedMemorySize, SMEM_ATTN);

    const int nHid  = TT * HID;
    const int nWqkv = QKVD * HID;
    const int nWo   = HID * HID;

    split_bf16<<<(nHid / 4 + 255) / 256, 256>>>(hidden, hid_hi, hid_lo, nHid / 4);
    split_bf16<<<(nWqkv / 4 + 255) / 256, 256>>>(wqkv, wqkv_hi, wqkv_lo, nWqkv / 4);

    gemm_mma<<<dim3(TT / GBM, QKVD / GBN), 256, GEMM_SMEM>>>(
        hid_hi, hid_lo, wqkv_hi, wqkv_lo, bqkv, qkv_ptr, TT, QKVD, HID);

    rope_kernel<<<dim3(NH + NKV, TT), 64>>>(qkv_ptr, positions);

    attn_kernel<<<dim3(TT / 64, NH), 256, SMEM_ATTN>>>(qkv_ptr, attn_ptr, window);

    split_bf16<<<(nHid / 4 + 255) / 256, 256>>>(attn_ptr, attn_hi, attn_lo, nHid / 4);
    split_bf16<<<(nWo / 4 + 255) / 256, 256>>>(wo, wo_hi, wo_lo, nWo / 4);

    gemm_mma<<<dim3(TT / GBM, HID / GBN), 256, GEMM_SMEM>>>(
        attn_hi, attn_lo, wo_hi, wo_lo, bo, out, TT, HID, HID);
}

// round 5
// speedup vs baseline: 1.7664x; 1.0130x over previous
#include <cuda_runtime.h>
#include <cuda_bf16.h>
#include <math.h>
#include <stdint.h>

#define TT 2048
#define HID 4608
#define NH 36
#define NKV 4
#define HD 128
#define QKVD 5632   // NH*HD + 2*NKV*HD
#define GROUP 9     // NH / NKV
#define ATT_SCALE 0.08838834764831843f
#define NEGINF (-1e30f)

// ---------------- scratch (no cudaMalloc allowed) ----------------
__device__ float g_qkv[TT * QKVD];
__device__ float g_attn[TT * NH * HD];
__device__ __nv_bfloat16 g_hid_hi[TT * HID];
__device__ __nv_bfloat16 g_hid_lo[TT * HID];
__device__ __nv_bfloat16 g_wqkv_hi[QKVD * HID];
__device__ __nv_bfloat16 g_wqkv_lo[QKVD * HID];
__device__ __nv_bfloat16 g_wo_hi[HID * HID];
__device__ __nv_bfloat16 g_wo_lo[HID * HID];
__device__ __nv_bfloat16 g_attn_hi[TT * HID];
__device__ __nv_bfloat16 g_attn_lo[TT * HID];

__device__ __forceinline__ uint32_t smem_u32(const void* p) {
    uint32_t a;
    asm("{ .reg .u64 t; cvta.to.shared.u64 t, %1; cvt.u32.u64 %0, t; }" : "=r"(a) : "l"(p));
    return a;
}

// ---------------------------------------------------------------------------
// fp32 -> bf16 hi/lo split
// ---------------------------------------------------------------------------
__global__ __launch_bounds__(256) void split_bf16(const float* __restrict__ x,
                                                  __nv_bfloat16* __restrict__ hi,
                                                  __nv_bfloat16* __restrict__ lo,
                                                  int n4)
{
    int i = blockIdx.x * 256 + threadIdx.x;
    if (i >= n4) return;
    float4 v = ((const float4*)x)[i];
    __nv_bfloat16 h0 = __float2bfloat16(v.x);
    __nv_bfloat16 h1 = __float2bfloat16(v.y);
    __nv_bfloat16 h2 = __float2bfloat16(v.z);
    __nv_bfloat16 h3 = __float2bfloat16(v.w);
    __nv_bfloat16 l0 = __float2bfloat16(v.x - __bfloat162float(h0));
    __nv_bfloat16 l1 = __float2bfloat16(v.y - __bfloat162float(h1));
    __nv_bfloat16 l2 = __float2bfloat16(v.z - __bfloat162float(h2));
    __nv_bfloat16 l3 = __float2bfloat16(v.w - __bfloat162float(h3));
    union { __nv_bfloat16 b[4]; uint2 u; } H, L;
    H.b[0] = h0; H.b[1] = h1; H.b[2] = h2; H.b[3] = h3;
    L.b[0] = l0; L.b[1] = l1; L.b[2] = l2; L.b[3] = l3;
    ((uint2*)hi)[i] = H.u;
    ((uint2*)lo)[i] = L.u;
}

// ---------------------------------------------------------------------------
// bf16x3 GEMM via mma.sync (HMMA):  C[m,n] = sum_k A[m,k]*B[n,k] + bias[n]
// 128x128 CTA tile, BK=32, 8 warps (2x4), each warp 64x32.
// 3-stage cp.async pipeline (wait_group 1 steady state).
// ---------------------------------------------------------------------------
#define GBM 128
#define GBN 128
#define GBK 32
#define ROWB 80                     // bytes per smem row (32 bf16 + 8 pad)
#define TILE_B (128 * ROWB)         // 10240 per operand tile
#define STAGE_B (4 * TILE_B)        // Ahi, Alo, Bhi, Blo = 40960
#define NSTG 3
#define GEMM_SMEM (NSTG * STAGE_B)  // 122880

__device__ __forceinline__ void ldm_x4(uint32_t* r, uint32_t addr) {
    asm volatile("ldmatrix.sync.aligned.m8n8.x4.shared.b16 {%0,%1,%2,%3}, [%4];"
                 : "=r"(r[0]), "=r"(r[1]), "=r"(r[2]), "=r"(r[3]) : "r"(addr));
}
__device__ __forceinline__ void mma16816(float* d, const uint32_t* a, uint32_t b0, uint32_t b1) {
    asm volatile(
        "mma.sync.aligned.m16n8k16.row.col.f32.bf16.bf16.f32 "
        "{%0,%1,%2,%3}, {%4,%5,%6,%7}, {%8,%9}, {%0,%1,%2,%3};"
        : "+f"(d[0]), "+f"(d[1]), "+f"(d[2]), "+f"(d[3])
        : "r"(a[0]), "r"(a[1]), "r"(a[2]), "r"(a[3]), "r"(b0), "r"(b1));
}

__global__ __launch_bounds__(256, 1) void gemm_mma(
    const __nv_bfloat16* __restrict__ Ahi, const __nv_bfloat16* __restrict__ Alo,
    const __nv_bfloat16* __restrict__ Bhi, const __nv_bfloat16* __restrict__ Blo,
    const float* __restrict__ bias, float* __restrict__ C,
    int M, int N, int K)
{
    extern __shared__ char smem[];
    const uint32_t sb = smem_u32(smem);
    const int tid = threadIdx.x, wid = tid >> 5, lane = tid & 31;
    const int warp_m = wid & 1;
    const int warp_n = wid >> 1;
    const int bm = blockIdx.x * GBM, bn = blockIdx.y * GBN;

    float acc[4][4][4];
#pragma unroll
    for (int i = 0; i < 4; i++)
#pragma unroll
        for (int j = 0; j < 4; j++)
#pragma unroll
            for (int q = 0; q < 4; q++) acc[i][j][q] = 0.0f;

    auto load_stage = [&](int stg, int k0) {
        uint32_t base = sb + stg * STAGE_B;
#pragma unroll
        for (int i = 0; i < 8; i++) {
            int c = tid + i * 256;
            int tile = c >> 9;          // 0:Ahi 1:Alo 2:Bhi 3:Blo
            int idx = c & 511;
            int row = idx >> 2, ch = idx & 3;
            const __nv_bfloat16* g;
            int grow;
            if (tile < 2) { g = tile ? Alo : Ahi; grow = bm + row; }
            else          { g = (tile == 3) ? Blo : Bhi; grow = bn + row; }
            const char* src = (const char*)(g + (size_t)grow * K + k0) + ch * 16;
            uint32_t dst = base + tile * TILE_B + row * ROWB + ch * 16;
            asm volatile("cp.async.cg.shared.global [%0], [%1], 16;" :: "r"(dst), "l"(src));
        }
        asm volatile("cp.async.commit_group;" ::: "memory");
    };

    const int NKB = K / GBK;
    load_stage(0, 0);
    load_stage(1, GBK);

    const int a_row = (lane & 15);
    const int a_kh = lane >> 4;
    const int b_nrow = (lane & 7) + ((lane >> 4) & 1) * 8;
    const int b_kh = (lane >> 3) & 1;

    for (int kb = 0; kb < NKB; kb++) {
        const int cur = kb % NSTG;
        if (kb + 1 < NKB) { asm volatile("cp.async.wait_group 1;" ::: "memory"); }
        else              { asm volatile("cp.async.wait_group 0;" ::: "memory"); }
        __syncthreads();

        if (kb + 2 < NKB) load_stage((kb + 2) % NSTG, (kb + 2) * GBK);

        const uint32_t stage = sb + cur * STAGE_B;
        const uint32_t Ah = stage;
        const uint32_t Al = stage + TILE_B;
        const uint32_t Bh = stage + 2 * TILE_B;
        const uint32_t Bl = stage + 3 * TILE_B;

#pragma unroll
        for (int ks = 0; ks < 2; ks++) {
            uint32_t ah[4][4], al[4][4];
#pragma unroll
            for (int mf = 0; mf < 4; mf++) {
                uint32_t off = (warp_m * 64 + mf * 16 + a_row) * ROWB + ks * 32 + a_kh * 16;
                ldm_x4(ah[mf], Ah + off);
                ldm_x4(al[mf], Al + off);
            }
            uint32_t bh[2][4], bl[2][4];
#pragma unroll
            for (int p = 0; p < 2; p++) {
                uint32_t off = (warp_n * 32 + p * 16 + b_nrow) * ROWB + ks * 32 + b_kh * 16;
                ldm_x4(bh[p], Bh + off);
                ldm_x4(bl[p], Bl + off);
            }
#pragma unroll
            for (int mf = 0; mf < 4; mf++) {
#pragma unroll
                for (int nf = 0; nf < 4; nf++) {
                    const int p = nf >> 1, o = (nf & 1) * 2;
                    mma16816(acc[mf][nf], ah[mf], bh[p][o], bh[p][o + 1]);
                    mma16816(acc[mf][nf], ah[mf], bl[p][o], bl[p][o + 1]);
                    mma16816(acc[mf][nf], al[mf], bh[p][o], bh[p][o + 1]);
                }
            }
        }
    }

    const int qr = lane >> 2, qc = (lane & 3) * 2;
#pragma unroll
    for (int mf = 0; mf < 4; mf++) {
        int row0 = bm + warp_m * 64 + mf * 16 + qr;
#pragma unroll
        for (int nf = 0; nf < 4; nf++) {
            int col = bn + warp_n * 32 + nf * 8 + qc;
            float2 bv = *(const float2*)(bias + col);
            float2 v0 = { acc[mf][nf][0] + bv.x, acc[mf][nf][1] + bv.y };
            float2 v1 = { acc[mf][nf][2] + bv.x, acc[mf][nf][3] + bv.y };
            *(float2*)(C + (size_t)row0 * N + col) = v0;
            *(float2*)(C + (size_t)(row0 + 8) * N + col) = v1;
        }
    }
}

// ---------------------------------------------------------------------------
// NeoX RoPE (merged: 4 heads per 256-thread block)
// ---------------------------------------------------------------------------
__global__ __launch_bounds__(256) void rope_kernel(float* __restrict__ qkv,
                                                   const int* __restrict__ positions)
{
    const int tid = threadIdx.x;
    const int d = tid & 63;
    const int hh = blockIdx.x * 4 + (tid >> 6);   // 0..39
    const int t = blockIdx.y;

    float* base;
    if (hh < NH) base = qkv + (size_t)t * QKVD + hh * HD;
    else         base = qkv + (size_t)t * QKVD + NH * HD + (hh - NH) * HD;

    const float pos = (float)positions[t];
    const float inv_freq = expf(-11.512925464970229f * ((float)d / 64.0f));
    const float ang = pos * inv_freq;
    float s, c;
    sincosf(ang, &s, &c);

    const float x1 = base[d];
    const float x2 = base[d + 64];
    base[d]      = x1 * c - x2 * s;
    base[d + 64] = x2 * c + x1 * s;
}

// ---------------------------------------------------------------------------
// Windowed causal flash attention (SIMT fp32 — proven round-3 kernel)
// ---------------------------------------------------------------------------
#define QS_STRIDE 129
#define KS_STRIDE 129
#define VS_STRIDE 128
#define PS_STRIDE 65
#define SMEM_ATTN ((64 * QS_STRIDE + 64 * KS_STRIDE + 64 * VS_STRIDE + 64 * PS_STRIDE) * 4)

__global__ __launch_bounds__(256) void attn_kernel(const float* __restrict__ qkv,
                                                   float* __restrict__ attnOut,
                                                   const int* __restrict__ winp)
{
    extern __shared__ float sm[];
    float* Qs = sm;
    float* Ks = Qs + 64 * QS_STRIDE;
    float* Vs = Ks + 64 * KS_STRIDE;
    float* Ps = Vs + 64 * VS_STRIDE;

    const int tid = threadIdx.x;
    const int tr = tid >> 4;
    const int tc = tid & 15;
    const int h = blockIdx.y;
    const int qt0 = blockIdx.x * 64;
    const int kvh = h / GROUP;
    const int window = *winp;

    for (int idx = tid; idx < 64 * 32; idx += 256) {
        int row = idx >> 5;
        int c4 = idx & 31;
        float4 v = *(const float4*)(qkv + (size_t)(qt0 + row) * QKVD + h * HD + c4 * 4);
        float* dst = Qs + row * QS_STRIDE + c4 * 4;
        dst[0] = v.x; dst[1] = v.y; dst[2] = v.z; dst[3] = v.w;
    }

    float m[4], l[4], O[4][8];
#pragma unroll
    for (int i = 0; i < 4; i++) {
        m[i] = NEGINF;
        l[i] = 0.0f;
#pragma unroll
        for (int d = 0; d < 8; d++) O[i][d] = 0.0f;
    }

    int sBegin = qt0 - window + 1;
    if (sBegin < 0) sBegin = 0;
    sBegin &= ~63;
    const int sEnd = qt0 + 63;

    const size_t kOff = (size_t)NH * HD + (size_t)kvh * HD;
    const size_t vOff = (size_t)NH * HD + (size_t)NKV * HD + (size_t)kvh * HD;

    for (int s0 = sBegin; s0 <= sEnd; s0 += 64) {
        __syncthreads();

        for (int idx = tid; idx < 64 * 32; idx += 256) {
            int row = idx >> 5;
            int c4 = idx & 31;
            float4 kv4 = *(const float4*)(qkv + (size_t)(s0 + row) * QKVD + kOff + c4 * 4);
            float* kd = Ks + row * KS_STRIDE + c4 * 4;
            kd[0] = kv4.x; kd[1] = kv4.y; kd[2] = kv4.z; kd[3] = kv4.w;
            float4 vv4 = *(const float4*)(qkv + (size_t)(s0 + row) * QKVD + vOff + c4 * 4);
            *(float4*)(Vs + row * VS_STRIDE + c4 * 4) = vv4;
        }
        __syncthreads();

        float S[4][4];
#pragma unroll
        for (int i = 0; i < 4; i++)
#pragma unroll
            for (int j = 0; j < 4; j++) S[i][j] = 0.0f;

#pragma unroll 4
        for (int kk = 0; kk < 128; kk++) {
            float a[4], b[4];
#pragma unroll
            for (int i = 0; i < 4; i++) a[i] = Qs[(4 * tr + i) * QS_STRIDE + kk];
#pragma unroll
            for (int j = 0; j < 4; j++) b[j] = Ks[(4 * tc + j) * KS_STRIDE + kk];
#pragma unroll
            for (int i = 0; i < 4; i++)
#pragma unroll
                for (int j = 0; j < 4; j++)
                    S[i][j] = fmaf(a[i], b[j], S[i][j]);
        }

#pragma unroll
        for (int i = 0; i < 4; i++) {
            int tq = qt0 + 4 * tr + i;
#pragma unroll
            for (int j = 0; j < 4; j++) {
                int sk = s0 + 4 * tc + j;
                bool ok = (sk <= tq) && (sk > tq - window);
                S[i][j] = ok ? S[i][j] * ATT_SCALE : NEGINF;
            }
        }

#pragma unroll
        for (int i = 0; i < 4; i++) {
            float tmax = fmaxf(fmaxf(S[i][0], S[i][1]), fmaxf(S[i][2], S[i][3]));
#pragma unroll
            for (int off = 8; off >= 1; off >>= 1)
                tmax = fmaxf(tmax, __shfl_xor_sync(0xffffffffu, tmax, off, 16));

            float mn = fmaxf(m[i], tmax);
            float corr = expf(m[i] - mn);
            m[i] = mn;

            float rsum = 0.0f;
#pragma unroll
            for (int j = 0; j < 4; j++) {
                S[i][j] = expf(S[i][j] - mn);
                rsum += S[i][j];
            }
#pragma unroll
            for (int off = 8; off >= 1; off >>= 1)
                rsum += __shfl_xor_sync(0xffffffffu, rsum, off, 16);

            l[i] = l[i] * corr + rsum;
#pragma unroll
            for (int d = 0; d < 8; d++) O[i][d] *= corr;

#pragma unroll
            for (int j = 0; j < 4; j++)
                Ps[(4 * tr + i) * PS_STRIDE + 4 * tc + j] = S[i][j];
        }
        __syncthreads();

#pragma unroll 4
        for (int kk = 0; kk < 64; kk++) {
            float a[4];
#pragma unroll
            for (int i = 0; i < 4; i++) a[i] = Ps[(4 * tr + i) * PS_STRIDE + kk];
            float4 v0 = *(const float4*)(Vs + kk * VS_STRIDE + tc * 8);
            float4 v1 = *(const float4*)(Vs + kk * VS_STRIDE + tc * 8 + 4);
            float b[8] = {v0.x, v0.y, v0.z, v0.w, v1.x, v1.y, v1.z, v1.w};
#pragma unroll
            for (int i = 0; i < 4; i++)
#pragma unroll
                for (int d = 0; d < 8; d++)
                    O[i][d] = fmaf(a[i], b[d], O[i][d]);
        }
    }

#pragma unroll
    for (int i = 0; i < 4; i++) {
        float inv = 1.0f / l[i];
        int row = qt0 + 4 * tr + i;
        float* dst = attnOut + (size_t)row * (NH * HD) + h * HD + tc * 8;
#pragma unroll
        for (int d = 0; d < 8; d++) dst[d] = O[i][d] * inv;
    }
}

// ---------------------------------------------------------------------------
extern "C" void kernel_launch(void* const* d_in, const int* in_sizes, int n_in,
                              void* d_out, int out_size)
{
    const int*   positions = (const int*)d_in[0];
    const float* hidden    = (const float*)d_in[1];
    const float* wqkv      = (const float*)d_in[2];
    const float* bqkv      = (const float*)d_in[3];
    const float* wo        = (const float*)d_in[4];
    const float* bo        = (const float*)d_in[5];
    const int*   window    = (const int*)d_in[6];
    float* out = (float*)d_out;

    float *qkv_ptr, *attn_ptr;
    __nv_bfloat16 *hid_hi, *hid_lo, *wqkv_hi, *wqkv_lo, *wo_hi, *wo_lo, *attn_hi, *attn_lo;
    cudaGetSymbolAddress((void**)&qkv_ptr,  g_qkv);
    cudaGetSymbolAddress((void**)&attn_ptr, g_attn);
    cudaGetSymbolAddress((void**)&hid_hi,   g_hid_hi);
    cudaGetSymbolAddress((void**)&hid_lo,   g_hid_lo);
    cudaGetSymbolAddress((void**)&wqkv_hi,  g_wqkv_hi);
    cudaGetSymbolAddress((void**)&wqkv_lo,  g_wqkv_lo);
    cudaGetSymbolAddress((void**)&wo_hi,    g_wo_hi);
    cudaGetSymbolAddress((void**)&wo_lo,    g_wo_lo);
    cudaGetSymbolAddress((void**)&attn_hi,  g_attn_hi);
    cudaGetSymbolAddress((void**)&attn_lo,  g_attn_lo);

    cudaFuncSetAttribute(gemm_mma, cudaFuncAttributeMaxDynamicSharedMemorySize, GEMM_SMEM);
    cudaFuncSetAttribute(attn_kernel, cudaFuncAttributeMaxDynamicSharedMemorySize, SMEM_ATTN);

    const int nHid  = TT * HID;
    const int nWqkv = QKVD * HID;
    const int nWo   = HID * HID;

    split_bf16<<<(nHid / 4 + 255) / 256, 256>>>(hidden, hid_hi, hid_lo, nHid / 4);
    split_bf16<<<(nWqkv / 4 + 255) / 256, 256>>>(wqkv, wqkv_hi, wqkv_lo, nWqkv / 4);

    gemm_mma<<<dim3(TT / GBM, QKVD / GBN), 256, GEMM_SMEM>>>(
        hid_hi, hid_lo, wqkv_hi, wqkv_lo, bqkv, qkv_ptr, TT, QKVD, HID);

    rope_kernel<<<dim3(10, TT), 256>>>(qkv_ptr, positions);

    attn_kernel<<<dim3(TT / 64, NH), 256, SMEM_ATTN>>>(qkv_ptr, attn_ptr, window);

    split_bf16<<<(nHid / 4 + 255) / 256, 256>>>(attn_ptr, attn_hi, attn_lo, nHid / 4);
    split_bf16<<<(nWo / 4 + 255) / 256, 256>>>(wo, wo_hi, wo_lo, nWo / 4);

    gemm_mma<<<dim3(TT / GBM, HID / GBN), 256, GEMM_SMEM>>>(
        attn_hi, attn_lo, wo_hi, wo_lo, bo, out, TT, HID, HID);
}

// round 6
// speedup vs baseline: 2.4353x; 1.3787x over previous
#include <cuda_runtime.h>
#include <cuda_bf16.h>
#include <math.h>
#include <stdint.h>

#define TT 2048
#define HID 4608
#define NH 36
#define NKV 4
#define HD 128
#define QKVD 5632
#define GROUP 9
#define ATT_SCALE 0.08838834764831843f
#define LOG2E 1.4426950408889634f

// ---------------- scratch ----------------
__device__ float g_qkv[TT * QKVD];
__device__ __nv_bfloat16 g_hid_hi[TT * HID];
__device__ __nv_bfloat16 g_hid_lo[TT * HID];
__device__ __nv_bfloat16 g_wqkv_hi[QKVD * HID];
__device__ __nv_bfloat16 g_wqkv_lo[QKVD * HID];
__device__ __nv_bfloat16 g_wo_hi[HID * HID];
__device__ __nv_bfloat16 g_wo_lo[HID * HID];
__device__ __nv_bfloat16 g_attn_hi[TT * HID];
__device__ __nv_bfloat16 g_attn_lo[TT * HID];

__device__ __forceinline__ uint32_t smem_u32(const void* p) {
    uint32_t a;
    asm("{ .reg .u64 t; cvta.to.shared.u64 t, %1; cvt.u32.u64 %0, t; }" : "=r"(a) : "l"(p));
    return a;
}
__device__ __forceinline__ void ldm_x4(uint32_t* r, uint32_t addr) {
    asm volatile("ldmatrix.sync.aligned.m8n8.x4.shared.b16 {%0,%1,%2,%3}, [%4];"
                 : "=r"(r[0]), "=r"(r[1]), "=r"(r[2]), "=r"(r[3]) : "r"(addr));
}
__device__ __forceinline__ void ldm_x4_t(uint32_t* r, uint32_t addr) {
    asm volatile("ldmatrix.sync.aligned.m8n8.x4.trans.shared.b16 {%0,%1,%2,%3}, [%4];"
                 : "=r"(r[0]), "=r"(r[1]), "=r"(r[2]), "=r"(r[3]) : "r"(addr));
}
__device__ __forceinline__ void mma16816(float* d, const uint32_t* a, uint32_t b0, uint32_t b1) {
    asm volatile(
        "mma.sync.aligned.m16n8k16.row.col.f32.bf16.bf16.f32 "
        "{%0,%1,%2,%3}, {%4,%5,%6,%7}, {%8,%9}, {%0,%1,%2,%3};"
        : "+f"(d[0]), "+f"(d[1]), "+f"(d[2]), "+f"(d[3])
        : "r"(a[0]), "r"(a[1]), "r"(a[2]), "r"(a[3]), "r"(b0), "r"(b1));
}
__device__ __forceinline__ uint32_t pack2(__nv_bfloat16 a, __nv_bfloat16 b) {
    __nv_bfloat162 t(a, b);
    return *reinterpret_cast<uint32_t*>(&t);
}
__device__ __forceinline__ void split4(float4 v, uint2& hi, uint2& lo) {
    __nv_bfloat16 h0 = __float2bfloat16(v.x), h1 = __float2bfloat16(v.y);
    __nv_bfloat16 h2 = __float2bfloat16(v.z), h3 = __float2bfloat16(v.w);
    __nv_bfloat16 l0 = __float2bfloat16(v.x - __bfloat162float(h0));
    __nv_bfloat16 l1 = __float2bfloat16(v.y - __bfloat162float(h1));
    __nv_bfloat16 l2 = __float2bfloat16(v.z - __bfloat162float(h2));
    __nv_bfloat16 l3 = __float2bfloat16(v.w - __bfloat162float(h3));
    hi.x = pack2(h0, h1); hi.y = pack2(h2, h3);
    lo.x = pack2(l0, l1); lo.y = pack2(l2, l3);
}

// ---------------------------------------------------------------------------
// fp32 -> bf16 hi/lo split
// ---------------------------------------------------------------------------
__global__ __launch_bounds__(256) void split_bf16(const float* __restrict__ x,
                                                  __nv_bfloat16* __restrict__ hi,
                                                  __nv_bfloat16* __restrict__ lo,
                                                  int n4)
{
    int i = blockIdx.x * 256 + threadIdx.x;
    if (i >= n4) return;
    float4 v = ((const float4*)x)[i];
    uint2 H, L;
    split4(v, H, L);
    ((uint2*)hi)[i] = H;
    ((uint2*)lo)[i] = L;
}

// ---------------------------------------------------------------------------
// bf16x3 GEMM via mma.sync (3-stage pipeline, round-5 proven)
// ---------------------------------------------------------------------------
#define GBM 128
#define GBN 128
#define GBK 32
#define ROWB 80
#define TILE_B (128 * ROWB)
#define STAGE_B (4 * TILE_B)
#define NSTG 3
#define GEMM_SMEM (NSTG * STAGE_B)

__global__ __launch_bounds__(256, 1) void gemm_mma(
    const __nv_bfloat16* __restrict__ Ahi, const __nv_bfloat16* __restrict__ Alo,
    const __nv_bfloat16* __restrict__ Bhi, const __nv_bfloat16* __restrict__ Blo,
    const float* __restrict__ bias, float* __restrict__ C,
    int M, int N, int K)
{
    extern __shared__ char smem[];
    const uint32_t sb = smem_u32(smem);
    const int tid = threadIdx.x, wid = tid >> 5, lane = tid & 31;
    const int warp_m = wid & 1;
    const int warp_n = wid >> 1;
    const int bm = blockIdx.x * GBM, bn = blockIdx.y * GBN;

    float acc[4][4][4];
#pragma unroll
    for (int i = 0; i < 4; i++)
#pragma unroll
        for (int j = 0; j < 4; j++)
#pragma unroll
            for (int q = 0; q < 4; q++) acc[i][j][q] = 0.0f;

    auto load_stage = [&](int stg, int k0) {
        uint32_t base = sb + stg * STAGE_B;
#pragma unroll
        for (int i = 0; i < 8; i++) {
            int c = tid + i * 256;
            int tile = c >> 9;
            int idx = c & 511;
            int row = idx >> 2, ch = idx & 3;
            const __nv_bfloat16* g;
            int grow;
            if (tile < 2) { g = tile ? Alo : Ahi; grow = bm + row; }
            else          { g = (tile == 3) ? Blo : Bhi; grow = bn + row; }
            const char* src = (const char*)(g + (size_t)grow * K + k0) + ch * 16;
            uint32_t dst = base + tile * TILE_B + row * ROWB + ch * 16;
            asm volatile("cp.async.cg.shared.global [%0], [%1], 16;" :: "r"(dst), "l"(src));
        }
        asm volatile("cp.async.commit_group;" ::: "memory");
    };

    const int NKB = K / GBK;
    load_stage(0, 0);
    load_stage(1, GBK);

    const int a_row = (lane & 15);
    const int a_kh = lane >> 4;
    const int b_nrow = (lane & 7) + ((lane >> 4) & 1) * 8;
    const int b_kh = (lane >> 3) & 1;

    for (int kb = 0; kb < NKB; kb++) {
        const int cur = kb % NSTG;
        if (kb + 1 < NKB) { asm volatile("cp.async.wait_group 1;" ::: "memory"); }
        else              { asm volatile("cp.async.wait_group 0;" ::: "memory"); }
        __syncthreads();

        if (kb + 2 < NKB) load_stage((kb + 2) % NSTG, (kb + 2) * GBK);

        const uint32_t stage = sb + cur * STAGE_B;
        const uint32_t Ah = stage;
        const uint32_t Al = stage + TILE_B;
        const uint32_t Bh = stage + 2 * TILE_B;
        const uint32_t Bl = stage + 3 * TILE_B;

#pragma unroll
        for (int ks = 0; ks < 2; ks++) {
            uint32_t ah[4][4], al[4][4];
#pragma unroll
            for (int mf = 0; mf < 4; mf++) {
                uint32_t off = (warp_m * 64 + mf * 16 + a_row) * ROWB + ks * 32 + a_kh * 16;
                ldm_x4(ah[mf], Ah + off);
                ldm_x4(al[mf], Al + off);
            }
            uint32_t bh[2][4], bl[2][4];
#pragma unroll
            for (int p = 0; p < 2; p++) {
                uint32_t off = (warp_n * 32 + p * 16 + b_nrow) * ROWB + ks * 32 + b_kh * 16;
                ldm_x4(bh[p], Bh + off);
                ldm_x4(bl[p], Bl + off);
            }
#pragma unroll
            for (int mf = 0; mf < 4; mf++) {
#pragma unroll
                for (int nf = 0; nf < 4; nf++) {
                    const int p = nf >> 1, o = (nf & 1) * 2;
                    mma16816(acc[mf][nf], ah[mf], bh[p][o], bh[p][o + 1]);
                    mma16816(acc[mf][nf], ah[mf], bl[p][o], bl[p][o + 1]);
                    mma16816(acc[mf][nf], al[mf], bh[p][o], bh[p][o + 1]);
                }
            }
        }
    }

    const int qr = lane >> 2, qc = (lane & 3) * 2;
#pragma unroll
    for (int mf = 0; mf < 4; mf++) {
        int row0 = bm + warp_m * 64 + mf * 16 + qr;
#pragma unroll
        for (int nf = 0; nf < 4; nf++) {
            int col = bn + warp_n * 32 + nf * 8 + qc;
            float2 bv = *(const float2*)(bias + col);
            float2 v0 = { acc[mf][nf][0] + bv.x, acc[mf][nf][1] + bv.y };
            float2 v1 = { acc[mf][nf][2] + bv.x, acc[mf][nf][3] + bv.y };
            *(float2*)(C + (size_t)row0 * N + col) = v0;
            *(float2*)(C + (size_t)(row0 + 8) * N + col) = v1;
        }
    }
}

// ---------------------------------------------------------------------------
// NeoX RoPE (4 heads per 256-thread block)
// ---------------------------------------------------------------------------
__global__ __launch_bounds__(256) void rope_kernel(float* __restrict__ qkv,
                                                   const int* __restrict__ positions)
{
    const int tid = threadIdx.x;
    const int d = tid & 63;
    const int hh = blockIdx.x * 4 + (tid >> 6);
    const int t = blockIdx.y;

    float* base;
    if (hh < NH) base = qkv + (size_t)t * QKVD + hh * HD;
    else         base = qkv + (size_t)t * QKVD + NH * HD + (hh - NH) * HD;

    const float pos = (float)positions[t];
    const float inv_freq = expf(-11.512925464970229f * ((float)d / 64.0f));
    const float ang = pos * inv_freq;
    float s, c;
    sincosf(ang, &s, &c);

    const float x1 = base[d];
    const float x2 = base[d + 64];
    base[d]      = x1 * c - x2 * s;
    base[d + 64] = x2 * c + x1 * s;
}

// ---------------------------------------------------------------------------
// Windowed causal flash attention on HMMA (bf16x3), with cross-lane l-reduce.
// grid (TT/128, NH), 256 threads (8 warps, 16 q-rows each).
// Writes attention output directly as bf16 hi/lo split.
// ---------------------------------------------------------------------------
#define AROWB 272
#define AQ_B (128 * AROWB)
#define AK_B (64 * AROWB)
#define ATTN_SMEM (AQ_B * 2 + AK_B * 4)

__global__ __launch_bounds__(256, 1) void attn_mma(
    const float* __restrict__ qkv,
    __nv_bfloat16* __restrict__ outHi,
    __nv_bfloat16* __restrict__ outLo,
    const int* __restrict__ winp)
{
    extern __shared__ char smem[];
    const uint32_t sb = smem_u32(smem);
    const uint32_t Qhi = sb,                Qlo = sb + AQ_B;
    const uint32_t Khi = sb + 2 * AQ_B,     Klo = Khi + AK_B;
    const uint32_t Vhi = Klo + AK_B,        Vlo = Vhi + AK_B;

    const int tid = threadIdx.x, w = tid >> 5, lane = tid & 31;
    const int h = blockIdx.y, qt0 = blockIdx.x * 128;
    const int kvh = h / GROUP;
    const int window = *winp;
    const int g = lane >> 2, qc2 = (lane & 3) * 2;

    const size_t qOff = (size_t)h * HD;
    const size_t kOff = (size_t)NH * HD + (size_t)kvh * HD;
    const size_t vOff = kOff + (size_t)NKV * HD;

    // load Q tile (128 x 128), split to hi/lo
    for (int idx = tid; idx < 128 * 32; idx += 256) {
        int row = idx >> 5, c4 = idx & 31;
        float4 v = *(const float4*)(qkv + (size_t)(qt0 + row) * QKVD + qOff + c4 * 4);
        uint2 H, L;
        split4(v, H, L);
        *(uint2*)(smem + (Qhi - sb) + row * AROWB + c4 * 8) = H;
        *(uint2*)(smem + (Qlo - sb) + row * AROWB + c4 * 8) = L;
    }

    float m0 = -1e30f, m1 = -1e30f, l0 = 0.0f, l1 = 0.0f;
    float O[16][4];
#pragma unroll
    for (int i = 0; i < 16; i++)
#pragma unroll
        for (int j = 0; j < 4; j++) O[i][j] = 0.0f;

    const int a_row = (lane & 15);
    const int a_kh = lane >> 4;
    const int b_nrow = (lane & 7) + ((lane >> 4) & 1) * 8;
    const int b_kh = (lane >> 3) & 1;
    const int vkr = (lane & 7) + ((lane >> 3) & 1) * 8;
    const int vnc = ((lane >> 4) & 1) * 8;

    const float sc = ATT_SCALE * LOG2E;
    const int qrow0 = qt0 + w * 16 + g;
    const int qrow1 = qrow0 + 8;

    int sBegin = qt0 - window + 1;
    if (sBegin < 0) sBegin = 0;
    sBegin &= ~63;
    const int sEnd = qt0 + 127;

    for (int s0 = sBegin; s0 <= sEnd; s0 += 64) {
        __syncthreads();
        for (int idx = tid; idx < 64 * 32; idx += 256) {
            int row = idx >> 5, c4 = idx & 31;
            float4 kv = *(const float4*)(qkv + (size_t)(s0 + row) * QKVD + kOff + c4 * 4);
            uint2 H, L;
            split4(kv, H, L);
            *(uint2*)(smem + (Khi - sb) + row * AROWB + c4 * 8) = H;
            *(uint2*)(smem + (Klo - sb) + row * AROWB + c4 * 8) = L;
            float4 vv = *(const float4*)(qkv + (size_t)(s0 + row) * QKVD + vOff + c4 * 4);
            split4(vv, H, L);
            *(uint2*)(smem + (Vhi - sb) + row * AROWB + c4 * 8) = H;
            *(uint2*)(smem + (Vlo - sb) + row * AROWB + c4 * 8) = L;
        }
        __syncthreads();

        // ---- S = Q K^T (16 x 64 per warp) ----
        float S[8][4];
#pragma unroll
        for (int i = 0; i < 8; i++)
#pragma unroll
            for (int j = 0; j < 4; j++) S[i][j] = 0.0f;

#pragma unroll
        for (int kf = 0; kf < 8; kf++) {
            uint32_t ah[4], al[4];
            uint32_t aoff = (w * 16 + a_row) * AROWB + kf * 32 + a_kh * 16;
            ldm_x4(ah, Qhi + aoff);
            ldm_x4(al, Qlo + aoff);
#pragma unroll
            for (int nt = 0; nt < 4; nt++) {
                uint32_t bh[4], bl[4];
                uint32_t boff = (nt * 16 + b_nrow) * AROWB + kf * 32 + b_kh * 16;
                ldm_x4(bh, Khi + boff);
                ldm_x4(bl, Klo + boff);
                mma16816(S[2 * nt],     ah, bh[0], bh[1]);
                mma16816(S[2 * nt + 1], ah, bh[2], bh[3]);
                mma16816(S[2 * nt],     ah, bl[0], bl[1]);
                mma16816(S[2 * nt + 1], ah, bl[2], bl[3]);
                mma16816(S[2 * nt],     al, bh[0], bh[1]);
                mma16816(S[2 * nt + 1], al, bh[2], bh[3]);
            }
        }

        // ---- scale + mask (log2 domain) ----
#pragma unroll
        for (int nf = 0; nf < 8; nf++) {
            int c0 = s0 + nf * 8 + qc2;
#pragma unroll
            for (int c = 0; c < 4; c++) {
                int col = c0 + (c & 1);
                int row = (c < 2) ? qrow0 : qrow1;
                bool ok = (col <= row) && (col > row - window);
                S[nf][c] = ok ? S[nf][c] * sc : -1e30f;
            }
        }

        // ---- online softmax ----
        float mx0 = -1e30f, mx1 = -1e30f;
#pragma unroll
        for (int nf = 0; nf < 8; nf++) {
            mx0 = fmaxf(mx0, fmaxf(S[nf][0], S[nf][1]));
            mx1 = fmaxf(mx1, fmaxf(S[nf][2], S[nf][3]));
        }
        mx0 = fmaxf(mx0, __shfl_xor_sync(0xffffffffu, mx0, 1));
        mx0 = fmaxf(mx0, __shfl_xor_sync(0xffffffffu, mx0, 2));
        mx1 = fmaxf(mx1, __shfl_xor_sync(0xffffffffu, mx1, 1));
        mx1 = fmaxf(mx1, __shfl_xor_sync(0xffffffffu, mx1, 2));

        float mn0 = fmaxf(m0, mx0), mn1 = fmaxf(m1, mx1);
        float corr0 = exp2f(m0 - mn0), corr1 = exp2f(m1 - mn1);
        m0 = mn0; m1 = mn1;

        uint32_t Phi[4][4], Plo[4][4];
        float rs0 = 0.0f, rs1 = 0.0f;
#pragma unroll
        for (int nf = 0; nf < 8; nf++) {
            float p0 = exp2f(S[nf][0] - mn0);
            float p1 = exp2f(S[nf][1] - mn0);
            float p2 = exp2f(S[nf][2] - mn1);
            float p3 = exp2f(S[nf][3] - mn1);
            rs0 += p0 + p1;
            rs1 += p2 + p3;
            __nv_bfloat16 h0 = __float2bfloat16(p0), h1 = __float2bfloat16(p1);
            __nv_bfloat16 h2 = __float2bfloat16(p2), h3 = __float2bfloat16(p3);
            __nv_bfloat16 e0 = __float2bfloat16(p0 - __bfloat162float(h0));
            __nv_bfloat16 e1 = __float2bfloat16(p1 - __bfloat162float(h1));
            __nv_bfloat16 e2 = __float2bfloat16(p2 - __bfloat162float(h2));
            __nv_bfloat16 e3 = __float2bfloat16(p3 - __bfloat162float(h3));
            const int kf = nf >> 1;
            if ((nf & 1) == 0) {
                Phi[kf][0] = pack2(h0, h1); Phi[kf][1] = pack2(h2, h3);
                Plo[kf][0] = pack2(e0, e1); Plo[kf][1] = pack2(e2, e3);
            } else {
                Phi[kf][2] = pack2(h0, h1); Phi[kf][3] = pack2(h2, h3);
                Plo[kf][2] = pack2(e0, e1); Plo[kf][3] = pack2(e2, e3);
            }
        }
        // FIX (round-4 bug): reduce partial row sums across the quad — each
        // lane holds only 16 of the row's 64 tile columns, but O's MMA
        // accumulator contains the full k-sum.
        rs0 += __shfl_xor_sync(0xffffffffu, rs0, 1);
        rs0 += __shfl_xor_sync(0xffffffffu, rs0, 2);
        rs1 += __shfl_xor_sync(0xffffffffu, rs1, 1);
        rs1 += __shfl_xor_sync(0xffffffffu, rs1, 2);

        l0 = l0 * corr0 + rs0;
        l1 = l1 * corr1 + rs1;
#pragma unroll
        for (int nf = 0; nf < 16; nf++) {
            O[nf][0] *= corr0; O[nf][1] *= corr0;
            O[nf][2] *= corr1; O[nf][3] *= corr1;
        }

        // ---- O += P V ----
#pragma unroll
        for (int kf = 0; kf < 4; kf++) {
#pragma unroll
            for (int nt = 0; nt < 8; nt++) {
                uint32_t vh[4], vl[4];
                uint32_t voff = (kf * 16 + vkr) * AROWB + (nt * 16 + vnc) * 2;
                ldm_x4_t(vh, Vhi + voff);
                ldm_x4_t(vl, Vlo + voff);
                mma16816(O[2 * nt],     Phi[kf], vh[0], vh[1]);
                mma16816(O[2 * nt + 1], Phi[kf], vh[2], vh[3]);
                mma16816(O[2 * nt],     Phi[kf], vl[0], vl[1]);
                mma16816(O[2 * nt + 1], Phi[kf], vl[2], vl[3]);
                mma16816(O[2 * nt],     Plo[kf], vh[0], vh[1]);
                mma16816(O[2 * nt + 1], Plo[kf], vh[2], vh[3]);
            }
        }
    }

    // ---- epilogue: normalize, split to bf16 hi/lo, store ----
    const float inv0 = 1.0f / l0, inv1 = 1.0f / l1;
#pragma unroll
    for (int nf = 0; nf < 16; nf++) {
        int col = nf * 8 + qc2;
        size_t base0 = (size_t)qrow0 * HID + h * HD + col;
        size_t base1 = (size_t)qrow1 * HID + h * HD + col;
        float x0 = O[nf][0] * inv0, x1 = O[nf][1] * inv0;
        float x2 = O[nf][2] * inv1, x3 = O[nf][3] * inv1;
        __nv_bfloat16 h0 = __float2bfloat16(x0), h1 = __float2bfloat16(x1);
        __nv_bfloat16 h2 = __float2bfloat16(x2), h3 = __float2bfloat16(x3);
        *(uint32_t*)(outHi + base0) = pack2(h0, h1);
        *(uint32_t*)(outHi + base1) = pack2(h2, h3);
        __nv_bfloat16 e0 = __float2bfloat16(x0 - __bfloat162float(h0));
        __nv_bfloat16 e1 = __float2bfloat16(x1 - __bfloat162float(h1));
        __nv_bfloat16 e2 = __float2bfloat16(x2 - __bfloat162float(h2));
        __nv_bfloat16 e3 = __float2bfloat16(x3 - __bfloat162float(h3));
        *(uint32_t*)(outLo + base0) = pack2(e0, e1);
        *(uint32_t*)(outLo + base1) = pack2(e2, e3);
    }
}

// ---------------------------------------------------------------------------
extern "C" void kernel_launch(void* const* d_in, const int* in_sizes, int n_in,
                              void* d_out, int out_size)
{
    const int*   positions = (const int*)d_in[0];
    const float* hidden    = (const float*)d_in[1];
    const float* wqkv      = (const float*)d_in[2];
    const float* bqkv      = (const float*)d_in[3];
    const float* wo        = (const float*)d_in[4];
    const float* bo        = (const float*)d_in[5];
    const int*   window    = (const int*)d_in[6];
    float* out = (float*)d_out;

    float* qkv_ptr;
    __nv_bfloat16 *hid_hi, *hid_lo, *wqkv_hi, *wqkv_lo, *wo_hi, *wo_lo, *attn_hi, *attn_lo;
    cudaGetSymbolAddress((void**)&qkv_ptr,  g_qkv);
    cudaGetSymbolAddress((void**)&hid_hi,   g_hid_hi);
    cudaGetSymbolAddress((void**)&hid_lo,   g_hid_lo);
    cudaGetSymbolAddress((void**)&wqkv_hi,  g_wqkv_hi);
    cudaGetSymbolAddress((void**)&wqkv_lo,  g_wqkv_lo);
    cudaGetSymbolAddress((void**)&wo_hi,    g_wo_hi);
    cudaGetSymbolAddress((void**)&wo_lo,    g_wo_lo);
    cudaGetSymbolAddress((void**)&attn_hi,  g_attn_hi);
    cudaGetSymbolAddress((void**)&attn_lo,  g_attn_lo);

    cudaFuncSetAttribute(gemm_mma, cudaFuncAttributeMaxDynamicSharedMemorySize, GEMM_SMEM);
    cudaFuncSetAttribute(attn_mma, cudaFuncAttributeMaxDynamicSharedMemorySize, ATTN_SMEM);

    const int nHid  = TT * HID;
    const int nWqkv = QKVD * HID;
    const int nWo   = HID * HID;

    split_bf16<<<(nHid / 4 + 255) / 256, 256>>>(hidden, hid_hi, hid_lo, nHid / 4);
    split_bf16<<<(nWqkv / 4 + 255) / 256, 256>>>(wqkv, wqkv_hi, wqkv_lo, nWqkv / 4);

    gemm_mma<<<dim3(TT / GBM, QKVD / GBN), 256, GEMM_SMEM>>>(
        hid_hi, hid_lo, wqkv_hi, wqkv_lo, bqkv, qkv_ptr, TT, QKVD, HID);

    rope_kernel<<<dim3(10, TT), 256>>>(qkv_ptr, positions);

    attn_mma<<<dim3(TT / 128, NH), 256, ATTN_SMEM>>>(qkv_ptr, attn_hi, attn_lo, window);

    split_bf16<<<(nWo / 4 + 255) / 256, 256>>>(wo, wo_hi, wo_lo, nWo / 4);

    gemm_mma<<<dim3(TT / GBM, HID / GBN), 256, GEMM_SMEM>>>(
        attn_hi, attn_lo, wo_hi, wo_lo, bo, out, TT, HID, HID);
}

// round 7
// speedup vs baseline: 2.4402x; 1.0020x over previous
#include <cuda_runtime.h>
#include <cuda_bf16.h>
#include <math.h>
#include <stdint.h>

#define TT 2048
#define HID 4608
#define NH 36
#define NKV 4
#define HD 128
#define QKVD 5632
#define GROUP 9
#define ATT_SCALE 0.08838834764831843f
#define LOG2E 1.4426950408889634f

// ---------------- scratch ----------------
__device__ float g_qkv[TT * QKVD];
__device__ __nv_bfloat16 g_hid_hi[TT * HID];
__device__ __nv_bfloat16 g_hid_lo[TT * HID];
__device__ __nv_bfloat16 g_wqkv_hi[QKVD * HID];
__device__ __nv_bfloat16 g_wqkv_lo[QKVD * HID];
__device__ __nv_bfloat16 g_wo_hi[HID * HID];
__device__ __nv_bfloat16 g_wo_lo[HID * HID];
__device__ __nv_bfloat16 g_attn_hi[TT * HID];
__device__ __nv_bfloat16 g_attn_lo[TT * HID];

__device__ __forceinline__ uint32_t smem_u32(const void* p) {
    uint32_t a;
    asm("{ .reg .u64 t; cvta.to.shared.u64 t, %1; cvt.u32.u64 %0, t; }" : "=r"(a) : "l"(p));
    return a;
}
__device__ __forceinline__ void ldm_x4(uint32_t* r, uint32_t addr) {
    asm volatile("ldmatrix.sync.aligned.m8n8.x4.shared.b16 {%0,%1,%2,%3}, [%4];"
                 : "=r"(r[0]), "=r"(r[1]), "=r"(r[2]), "=r"(r[3]) : "r"(addr));
}
__device__ __forceinline__ void ldm_x4_t(uint32_t* r, uint32_t addr) {
    asm volatile("ldmatrix.sync.aligned.m8n8.x4.trans.shared.b16 {%0,%1,%2,%3}, [%4];"
                 : "=r"(r[0]), "=r"(r[1]), "=r"(r[2]), "=r"(r[3]) : "r"(addr));
}
__device__ __forceinline__ void mma16816(float* d, const uint32_t* a, uint32_t b0, uint32_t b1) {
    asm volatile(
        "mma.sync.aligned.m16n8k16.row.col.f32.bf16.bf16.f32 "
        "{%0,%1,%2,%3}, {%4,%5,%6,%7}, {%8,%9}, {%0,%1,%2,%3};"
        : "+f"(d[0]), "+f"(d[1]), "+f"(d[2]), "+f"(d[3])
        : "r"(a[0]), "r"(a[1]), "r"(a[2]), "r"(a[3]), "r"(b0), "r"(b1));
}
__device__ __forceinline__ uint32_t pack2(__nv_bfloat16 a, __nv_bfloat16 b) {
    __nv_bfloat162 t(a, b);
    return *reinterpret_cast<uint32_t*>(&t);
}
__device__ __forceinline__ void split4(float4 v, uint2& hi, uint2& lo) {
    __nv_bfloat16 h0 = __float2bfloat16(v.x), h1 = __float2bfloat16(v.y);
    __nv_bfloat16 h2 = __float2bfloat16(v.z), h3 = __float2bfloat16(v.w);
    __nv_bfloat16 l0 = __float2bfloat16(v.x - __bfloat162float(h0));
    __nv_bfloat16 l1 = __float2bfloat16(v.y - __bfloat162float(h1));
    __nv_bfloat16 l2 = __float2bfloat16(v.z - __bfloat162float(h2));
    __nv_bfloat16 l3 = __float2bfloat16(v.w - __bfloat162float(h3));
    hi.x = pack2(h0, h1); hi.y = pack2(h2, h3);
    lo.x = pack2(l0, l1); lo.y = pack2(l2, l3);
}

// ---------------------------------------------------------------------------
// fp32 -> bf16 hi/lo split
// ---------------------------------------------------------------------------
__global__ __launch_bounds__(256) void split_bf16(const float* __restrict__ x,
                                                  __nv_bfloat16* __restrict__ hi,
                                                  __nv_bfloat16* __restrict__ lo,
                                                  int n4)
{
    int i = blockIdx.x * 256 + threadIdx.x;
    if (i >= n4) return;
    float4 v = ((const float4*)x)[i];
    uint2 H, L;
    split4(v, H, L);
    ((uint2*)hi)[i] = H;
    ((uint2*)lo)[i] = L;
}

// ---------------------------------------------------------------------------
// bf16x3 GEMM via mma.sync — TERM-MAJOR inner loop (RAW chains broken).
// ---------------------------------------------------------------------------
#define GBM 128
#define GBN 128
#define GBK 32
#define ROWB 80
#define TILE_B (128 * ROWB)
#define STAGE_B (4 * TILE_B)
#define NSTG 3
#define GEMM_SMEM (NSTG * STAGE_B)

__global__ __launch_bounds__(256, 1) void gemm_mma(
    const __nv_bfloat16* __restrict__ Ahi, const __nv_bfloat16* __restrict__ Alo,
    const __nv_bfloat16* __restrict__ Bhi, const __nv_bfloat16* __restrict__ Blo,
    const float* __restrict__ bias, float* __restrict__ C,
    int M, int N, int K)
{
    extern __shared__ char smem[];
    const uint32_t sb = smem_u32(smem);
    const int tid = threadIdx.x, wid = tid >> 5, lane = tid & 31;
    const int warp_m = wid & 1;
    const int warp_n = wid >> 1;
    const int bm = blockIdx.x * GBM, bn = blockIdx.y * GBN;

    float acc[4][4][4];
#pragma unroll
    for (int i = 0; i < 4; i++)
#pragma unroll
        for (int j = 0; j < 4; j++)
#pragma unroll
            for (int q = 0; q < 4; q++) acc[i][j][q] = 0.0f;

    auto load_stage = [&](int stg, int k0) {
        uint32_t base = sb + stg * STAGE_B;
#pragma unroll
        for (int i = 0; i < 8; i++) {
            int c = tid + i * 256;
            int tile = c >> 9;
            int idx = c & 511;
            int row = idx >> 2, ch = idx & 3;
            const __nv_bfloat16* g;
            int grow;
            if (tile < 2) { g = tile ? Alo : Ahi; grow = bm + row; }
            else          { g = (tile == 3) ? Blo : Bhi; grow = bn + row; }
            const char* src = (const char*)(g + (size_t)grow * K + k0) + ch * 16;
            uint32_t dst = base + tile * TILE_B + row * ROWB + ch * 16;
            asm volatile("cp.async.cg.shared.global [%0], [%1], 16;" :: "r"(dst), "l"(src));
        }
        asm volatile("cp.async.commit_group;" ::: "memory");
    };

    const int NKB = K / GBK;
    load_stage(0, 0);
    load_stage(1, GBK);

    const int a_row = (lane & 15);
    const int a_kh = lane >> 4;
    const int b_nrow = (lane & 7) + ((lane >> 4) & 1) * 8;
    const int b_kh = (lane >> 3) & 1;

    for (int kb = 0; kb < NKB; kb++) {
        const int cur = kb % NSTG;
        if (kb + 1 < NKB) { asm volatile("cp.async.wait_group 1;" ::: "memory"); }
        else              { asm volatile("cp.async.wait_group 0;" ::: "memory"); }
        __syncthreads();

        if (kb + 2 < NKB) load_stage((kb + 2) % NSTG, (kb + 2) * GBK);

        const uint32_t stage = sb + cur * STAGE_B;
        const uint32_t Ah = stage;
        const uint32_t Al = stage + TILE_B;
        const uint32_t Bh = stage + 2 * TILE_B;
        const uint32_t Bl = stage + 3 * TILE_B;

#pragma unroll
        for (int ks = 0; ks < 2; ks++) {
            uint32_t ah[4][4], al[4][4];
#pragma unroll
            for (int mf = 0; mf < 4; mf++) {
                uint32_t off = (warp_m * 64 + mf * 16 + a_row) * ROWB + ks * 32 + a_kh * 16;
                ldm_x4(ah[mf], Ah + off);
                ldm_x4(al[mf], Al + off);
            }
            uint32_t bh[2][4], bl[2][4];
#pragma unroll
            for (int p = 0; p < 2; p++) {
                uint32_t off = (warp_n * 32 + p * 16 + b_nrow) * ROWB + ks * 32 + b_kh * 16;
                ldm_x4(bh[p], Bh + off);
                ldm_x4(bl[p], Bl + off);
            }
            // term-major: 16 independent MMAs per group, no back-to-back
            // accumulator reuse (RAW distance = 16 instead of 1).
#pragma unroll
            for (int mf = 0; mf < 4; mf++)
#pragma unroll
                for (int nf = 0; nf < 4; nf++) {
                    const int p = nf >> 1, o = (nf & 1) * 2;
                    mma16816(acc[mf][nf], ah[mf], bh[p][o], bh[p][o + 1]);  // hi*hi
                }
#pragma unroll
            for (int mf = 0; mf < 4; mf++)
#pragma unroll
                for (int nf = 0; nf < 4; nf++) {
                    const int p = nf >> 1, o = (nf & 1) * 2;
                    mma16816(acc[mf][nf], ah[mf], bl[p][o], bl[p][o + 1]);  // hi*lo
                }
#pragma unroll
            for (int mf = 0; mf < 4; mf++)
#pragma unroll
                for (int nf = 0; nf < 4; nf++) {
                    const int p = nf >> 1, o = (nf & 1) * 2;
                    mma16816(acc[mf][nf], al[mf], bh[p][o], bh[p][o + 1]);  // lo*hi
                }
        }
    }

    const int qr = lane >> 2, qc = (lane & 3) * 2;
#pragma unroll
    for (int mf = 0; mf < 4; mf++) {
        int row0 = bm + warp_m * 64 + mf * 16 + qr;
#pragma unroll
        for (int nf = 0; nf < 4; nf++) {
            int col = bn + warp_n * 32 + nf * 8 + qc;
            float2 bv = *(const float2*)(bias + col);
            float2 v0 = { acc[mf][nf][0] + bv.x, acc[mf][nf][1] + bv.y };
            float2 v1 = { acc[mf][nf][2] + bv.x, acc[mf][nf][3] + bv.y };
            *(float2*)(C + (size_t)row0 * N + col) = v0;
            *(float2*)(C + (size_t)(row0 + 8) * N + col) = v1;
        }
    }
}

// ---------------------------------------------------------------------------
// NeoX RoPE (4 heads per 256-thread block)
// ---------------------------------------------------------------------------
__global__ __launch_bounds__(256) void rope_kernel(float* __restrict__ qkv,
                                                   const int* __restrict__ positions)
{
    const int tid = threadIdx.x;
    const int d = tid & 63;
    const int hh = blockIdx.x * 4 + (tid >> 6);
    const int t = blockIdx.y;

    float* base;
    if (hh < NH) base = qkv + (size_t)t * QKVD + hh * HD;
    else         base = qkv + (size_t)t * QKVD + NH * HD + (hh - NH) * HD;

    const float pos = (float)positions[t];
    const float inv_freq = expf(-11.512925464970229f * ((float)d / 64.0f));
    const float ang = pos * inv_freq;
    float s, c;
    sincosf(ang, &s, &c);

    const float x1 = base[d];
    const float x2 = base[d + 64];
    base[d]      = x1 * c - x2 * s;
    base[d + 64] = x2 * c + x1 * s;
}

// ---------------------------------------------------------------------------
// Windowed causal flash attention on HMMA (bf16x3) — round-6 proven.
// ---------------------------------------------------------------------------
#define AROWB 272
#define AQ_B (128 * AROWB)
#define AK_B (64 * AROWB)
#define ATTN_SMEM (AQ_B * 2 + AK_B * 4)

__global__ __launch_bounds__(256, 1) void attn_mma(
    const float* __restrict__ qkv,
    __nv_bfloat16* __restrict__ outHi,
    __nv_bfloat16* __restrict__ outLo,
    const int* __restrict__ winp)
{
    extern __shared__ char smem[];
    const uint32_t sb = smem_u32(smem);
    const uint32_t Qhi = sb,                Qlo = sb + AQ_B;
    const uint32_t Khi = sb + 2 * AQ_B,     Klo = Khi + AK_B;
    const uint32_t Vhi = Klo + AK_B,        Vlo = Vhi + AK_B;

    const int tid = threadIdx.x, w = tid >> 5, lane = tid & 31;
    const int h = blockIdx.y, qt0 = blockIdx.x * 128;
    const int kvh = h / GROUP;
    const int window = *winp;
    const int g = lane >> 2, qc2 = (lane & 3) * 2;

    const size_t qOff = (size_t)h * HD;
    const size_t kOff = (size_t)NH * HD + (size_t)kvh * HD;
    const size_t vOff = kOff + (size_t)NKV * HD;

    for (int idx = tid; idx < 128 * 32; idx += 256) {
        int row = idx >> 5, c4 = idx & 31;
        float4 v = *(const float4*)(qkv + (size_t)(qt0 + row) * QKVD + qOff + c4 * 4);
        uint2 H, L;
        split4(v, H, L);
        *(uint2*)(smem + (Qhi - sb) + row * AROWB + c4 * 8) = H;
        *(uint2*)(smem + (Qlo - sb) + row * AROWB + c4 * 8) = L;
    }

    float m0 = -1e30f, m1 = -1e30f, l0 = 0.0f, l1 = 0.0f;
    float O[16][4];
#pragma unroll
    for (int i = 0; i < 16; i++)
#pragma unroll
        for (int j = 0; j < 4; j++) O[i][j] = 0.0f;

    const int a_row = (lane & 15);
    const int a_kh = lane >> 4;
    const int b_nrow = (lane & 7) + ((lane >> 4) & 1) * 8;
    const int b_kh = (lane >> 3) & 1;
    const int vkr = (lane & 7) + ((lane >> 3) & 1) * 8;
    const int vnc = ((lane >> 4) & 1) * 8;

    const float sc = ATT_SCALE * LOG2E;
    const int qrow0 = qt0 + w * 16 + g;
    const int qrow1 = qrow0 + 8;

    int sBegin = qt0 - window + 1;
    if (sBegin < 0) sBegin = 0;
    sBegin &= ~63;
    const int sEnd = qt0 + 127;

    for (int s0 = sBegin; s0 <= sEnd; s0 += 64) {
        __syncthreads();
        for (int idx = tid; idx < 64 * 32; idx += 256) {
            int row = idx >> 5, c4 = idx & 31;
            float4 kv = *(const float4*)(qkv + (size_t)(s0 + row) * QKVD + kOff + c4 * 4);
            uint2 H, L;
            split4(kv, H, L);
            *(uint2*)(smem + (Khi - sb) + row * AROWB + c4 * 8) = H;
            *(uint2*)(smem + (Klo - sb) + row * AROWB + c4 * 8) = L;
            float4 vv = *(const float4*)(qkv + (size_t)(s0 + row) * QKVD + vOff + c4 * 4);
            split4(vv, H, L);
            *(uint2*)(smem + (Vhi - sb) + row * AROWB + c4 * 8) = H;
            *(uint2*)(smem + (Vlo - sb) + row * AROWB + c4 * 8) = L;
        }
        __syncthreads();

        float S[8][4];
#pragma unroll
        for (int i = 0; i < 8; i++)
#pragma unroll
            for (int j = 0; j < 4; j++) S[i][j] = 0.0f;

#pragma unroll
        for (int kf = 0; kf < 8; kf++) {
            uint32_t ah[4], al[4];
            uint32_t aoff = (w * 16 + a_row) * AROWB + kf * 32 + a_kh * 16;
            ldm_x4(ah, Qhi + aoff);
            ldm_x4(al, Qlo + aoff);
#pragma unroll
            for (int nt = 0; nt < 4; nt++) {
                uint32_t bh[4], bl[4];
                uint32_t boff = (nt * 16 + b_nrow) * AROWB + kf * 32 + b_kh * 16;
                ldm_x4(bh, Khi + boff);
                ldm_x4(bl, Klo + boff);
                mma16816(S[2 * nt],     ah, bh[0], bh[1]);
                mma16816(S[2 * nt + 1], ah, bh[2], bh[3]);
                mma16816(S[2 * nt],     ah, bl[0], bl[1]);
                mma16816(S[2 * nt + 1], ah, bl[2], bl[3]);
                mma16816(S[2 * nt],     al, bh[0], bh[1]);
                mma16816(S[2 * nt + 1], al, bh[2], bh[3]);
            }
        }

#pragma unroll
        for (int nf = 0; nf < 8; nf++) {
            int c0 = s0 + nf * 8 + qc2;
#pragma unroll
            for (int c = 0; c < 4; c++) {
                int col = c0 + (c & 1);
                int row = (c < 2) ? qrow0 : qrow1;
                bool ok = (col <= row) && (col > row - window);
                S[nf][c] = ok ? S[nf][c] * sc : -1e30f;
            }
        }

        float mx0 = -1e30f, mx1 = -1e30f;
#pragma unroll
        for (int nf = 0; nf < 8; nf++) {
            mx0 = fmaxf(mx0, fmaxf(S[nf][0], S[nf][1]));
            mx1 = fmaxf(mx1, fmaxf(S[nf][2], S[nf][3]));
        }
        mx0 = fmaxf(mx0, __shfl_xor_sync(0xffffffffu, mx0, 1));
        mx0 = fmaxf(mx0, __shfl_xor_sync(0xffffffffu, mx0, 2));
        mx1 = fmaxf(mx1, __shfl_xor_sync(0xffffffffu, mx1, 1));
        mx1 = fmaxf(mx1, __shfl_xor_sync(0xffffffffu, mx1, 2));

        float mn0 = fmaxf(m0, mx0), mn1 = fmaxf(m1, mx1);
        float corr0 = exp2f(m0 - mn0), corr1 = exp2f(m1 - mn1);
        m0 = mn0; m1 = mn1;

        uint32_t Phi[4][4], Plo[4][4];
        float rs0 = 0.0f, rs1 = 0.0f;
#pragma unroll
        for (int nf = 0; nf < 8; nf++) {
            float p0 = exp2f(S[nf][0] - mn0);
            float p1 = exp2f(S[nf][1] - mn0);
            float p2 = exp2f(S[nf][2] - mn1);
            float p3 = exp2f(S[nf][3] - mn1);
            rs0 += p0 + p1;
            rs1 += p2 + p3;
            __nv_bfloat16 h0 = __float2bfloat16(p0), h1 = __float2bfloat16(p1);
            __nv_bfloat16 h2 = __float2bfloat16(p2), h3 = __float2bfloat16(p3);
            __nv_bfloat16 e0 = __float2bfloat16(p0 - __bfloat162float(h0));
            __nv_bfloat16 e1 = __float2bfloat16(p1 - __bfloat162float(h1));
            __nv_bfloat16 e2 = __float2bfloat16(p2 - __bfloat162float(h2));
            __nv_bfloat16 e3 = __float2bfloat16(p3 - __bfloat162float(h3));
            const int kf = nf >> 1;
            if ((nf & 1) == 0) {
                Phi[kf][0] = pack2(h0, h1); Phi[kf][1] = pack2(h2, h3);
                Plo[kf][0] = pack2(e0, e1); Plo[kf][1] = pack2(e2, e3);
            } else {
                Phi[kf][2] = pack2(h0, h1); Phi[kf][3] = pack2(h2, h3);
                Plo[kf][2] = pack2(e0, e1); Plo[kf][3] = pack2(e2, e3);
            }
        }
        rs0 += __shfl_xor_sync(0xffffffffu, rs0, 1);
        rs0 += __shfl_xor_sync(0xffffffffu, rs0, 2);
        rs1 += __shfl_xor_sync(0xffffffffu, rs1, 1);
        rs1 += __shfl_xor_sync(0xffffffffu, rs1, 2);

        l0 = l0 * corr0 + rs0;
        l1 = l1 * corr1 + rs1;
#pragma unroll
        for (int nf = 0; nf < 16; nf++) {
            O[nf][0] *= corr0; O[nf][1] *= corr0;
            O[nf][2] *= corr1; O[nf][3] *= corr1;
        }

#pragma unroll
        for (int kf = 0; kf < 4; kf++) {
#pragma unroll
            for (int nt = 0; nt < 8; nt++) {
                uint32_t vh[4], vl[4];
                uint32_t voff = (kf * 16 + vkr) * AROWB + (nt * 16 + vnc) * 2;
                ldm_x4_t(vh, Vhi + voff);
                ldm_x4_t(vl, Vlo + voff);
                mma16816(O[2 * nt],     Phi[kf], vh[0], vh[1]);
                mma16816(O[2 * nt + 1], Phi[kf], vh[2], vh[3]);
                mma16816(O[2 * nt],     Phi[kf], vl[0], vl[1]);
                mma16816(O[2 * nt + 1], Phi[kf], vl[2], vl[3]);
                mma16816(O[2 * nt],     Plo[kf], vh[0], vh[1]);
                mma16816(O[2 * nt + 1], Plo[kf], vh[2], vh[3]);
            }
        }
    }

    const float inv0 = 1.0f / l0, inv1 = 1.0f / l1;
#pragma unroll
    for (int nf = 0; nf < 16; nf++) {
        int col = nf * 8 + qc2;
        size_t base0 = (size_t)qrow0 * HID + h * HD + col;
        size_t base1 = (size_t)qrow1 * HID + h * HD + col;
        float x0 = O[nf][0] * inv0, x1 = O[nf][1] * inv0;
        float x2 = O[nf][2] * inv1, x3 = O[nf][3] * inv1;
        __nv_bfloat16 h0 = __float2bfloat16(x0), h1 = __float2bfloat16(x1);
        __nv_bfloat16 h2 = __float2bfloat16(x2), h3 = __float2bfloat16(x3);
        *(uint32_t*)(outHi + base0) = pack2(h0, h1);
        *(uint32_t*)(outHi + base1) = pack2(h2, h3);
        __nv_bfloat16 e0 = __float2bfloat16(x0 - __bfloat162float(h0));
        __nv_bfloat16 e1 = __float2bfloat16(x1 - __bfloat162float(h1));
        __nv_bfloat16 e2 = __float2bfloat16(x2 - __bfloat162float(h2));
        __nv_bfloat16 e3 = __float2bfloat16(x3 - __bfloat162float(h3));
        *(uint32_t*)(outLo + base0) = pack2(e0, e1);
        *(uint32_t*)(outLo + base1) = pack2(e2, e3);
    }
}

// ---------------------------------------------------------------------------
extern "C" void kernel_launch(void* const* d_in, const int* in_sizes, int n_in,
                              void* d_out, int out_size)
{
    const int*   positions = (const int*)d_in[0];
    const float* hidden    = (const float*)d_in[1];
    const float* wqkv      = (const float*)d_in[2];
    const float* bqkv      = (const float*)d_in[3];
    const float* wo        = (const float*)d_in[4];
    const float* bo        = (const float*)d_in[5];
    const int*   window    = (const int*)d_in[6];
    float* out = (float*)d_out;

    float* qkv_ptr;
    __nv_bfloat16 *hid_hi, *hid_lo, *wqkv_hi, *wqkv_lo, *wo_hi, *wo_lo, *attn_hi, *attn_lo;
    cudaGetSymbolAddress((void**)&qkv_ptr,  g_qkv);
    cudaGetSymbolAddress((void**)&hid_hi,   g_hid_hi);
    cudaGetSymbolAddress((void**)&hid_lo,   g_hid_lo);
    cudaGetSymbolAddress((void**)&wqkv_hi,  g_wqkv_hi);
    cudaGetSymbolAddress((void**)&wqkv_lo,  g_wqkv_lo);
    cudaGetSymbolAddress((void**)&wo_hi,    g_wo_hi);
    cudaGetSymbolAddress((void**)&wo_lo,    g_wo_lo);
    cudaGetSymbolAddress((void**)&attn_hi,  g_attn_hi);
    cudaGetSymbolAddress((void**)&attn_lo,  g_attn_lo);

    cudaFuncSetAttribute(gemm_mma, cudaFuncAttributeMaxDynamicSharedMemorySize, GEMM_SMEM);
    cudaFuncSetAttribute(attn_mma, cudaFuncAttributeMaxDynamicSharedMemorySize, ATTN_SMEM);

    const int nHid  = TT * HID;
    const int nWqkv = QKVD * HID;
    const int nWo   = HID * HID;

    split_bf16<<<(nHid / 4 + 255) / 256, 256>>>(hidden, hid_hi, hid_lo, nHid / 4);
    split_bf16<<<(nWqkv / 4 + 255) / 256, 256>>>(wqkv, wqkv_hi, wqkv_lo, nWqkv / 4);

    gemm_mma<<<dim3(TT / GBM, QKVD / GBN), 256, GEMM_SMEM>>>(
        hid_hi, hid_lo, wqkv_hi, wqkv_lo, bqkv, qkv_ptr, TT, QKVD, HID);

    rope_kernel<<<dim3(10, TT), 256>>>(qkv_ptr, positions);

    attn_mma<<<dim3(TT / 128, NH), 256, ATTN_SMEM>>>(qkv_ptr, attn_hi, attn_lo, window);

    split_bf16<<<(nWo / 4 + 255) / 256, 256>>>(wo, wo_hi, wo_lo, nWo / 4);

    gemm_mma<<<dim3(TT / GBM, HID / GBN), 256, GEMM_SMEM>>>(
        attn_hi, attn_lo, wo_hi, wo_lo, bo, out, TT, HID, HID);
}

// round 8
// speedup vs baseline: 2.5868x; 1.0601x over previous
#include <cuda_runtime.h>
#include <cuda_bf16.h>
#include <math.h>
#include <stdint.h>

#define TT 2048
#define HID 4608
#define NH 36
#define NKV 4
#define HD 128
#define QKVD 5632
#define GROUP 9
#define ATT_SCALE 0.08838834764831843f
#define LOG2E 1.4426950408889634f

// ---------------- scratch ----------------
__device__ float g_qkv[TT * QKVD];
__device__ __nv_bfloat16 g_hid_hi[TT * HID];
__device__ __nv_bfloat16 g_hid_lo[TT * HID];
__device__ __nv_bfloat16 g_wqkv_hi[QKVD * HID];
__device__ __nv_bfloat16 g_wqkv_lo[QKVD * HID];
__device__ __nv_bfloat16 g_wo_hi[HID * HID];
__device__ __nv_bfloat16 g_wo_lo[HID * HID];
__device__ __nv_bfloat16 g_attn_hi[TT * HID];
__device__ __nv_bfloat16 g_attn_lo[TT * HID];

__device__ __forceinline__ uint32_t smem_u32(const void* p) {
    uint32_t a;
    asm("{ .reg .u64 t; cvta.to.shared.u64 t, %1; cvt.u32.u64 %0, t; }" : "=r"(a) : "l"(p));
    return a;
}
__device__ __forceinline__ void ldm_x4(uint32_t* r, uint32_t addr) {
    asm volatile("ldmatrix.sync.aligned.m8n8.x4.shared.b16 {%0,%1,%2,%3}, [%4];"
                 : "=r"(r[0]), "=r"(r[1]), "=r"(r[2]), "=r"(r[3]) : "r"(addr));
}
__device__ __forceinline__ void ldm_x4_t(uint32_t* r, uint32_t addr) {
    asm volatile("ldmatrix.sync.aligned.m8n8.x4.trans.shared.b16 {%0,%1,%2,%3}, [%4];"
                 : "=r"(r[0]), "=r"(r[1]), "=r"(r[2]), "=r"(r[3]) : "r"(addr));
}
__device__ __forceinline__ void mma16816(float* d, const uint32_t* a, uint32_t b0, uint32_t b1) {
    asm volatile(
        "mma.sync.aligned.m16n8k16.row.col.f32.bf16.bf16.f32 "
        "{%0,%1,%2,%3}, {%4,%5,%6,%7}, {%8,%9}, {%0,%1,%2,%3};"
        : "+f"(d[0]), "+f"(d[1]), "+f"(d[2]), "+f"(d[3])
        : "r"(a[0]), "r"(a[1]), "r"(a[2]), "r"(a[3]), "r"(b0), "r"(b1));
}
__device__ __forceinline__ uint32_t pack2(__nv_bfloat16 a, __nv_bfloat16 b) {
    __nv_bfloat162 t(a, b);
    return *reinterpret_cast<uint32_t*>(&t);
}
__device__ __forceinline__ void split4(float4 v, uint2& hi, uint2& lo) {
    __nv_bfloat16 h0 = __float2bfloat16(v.x), h1 = __float2bfloat16(v.y);
    __nv_bfloat16 h2 = __float2bfloat16(v.z), h3 = __float2bfloat16(v.w);
    __nv_bfloat16 l0 = __float2bfloat16(v.x - __bfloat162float(h0));
    __nv_bfloat16 l1 = __float2bfloat16(v.y - __bfloat162float(h1));
    __nv_bfloat16 l2 = __float2bfloat16(v.z - __bfloat162float(h2));
    __nv_bfloat16 l3 = __float2bfloat16(v.w - __bfloat162float(h3));
    hi.x = pack2(h0, h1); hi.y = pack2(h2, h3);
    lo.x = pack2(l0, l1); lo.y = pack2(l2, l3);
}

// ---------------------------------------------------------------------------
// fp32 -> bf16 hi/lo split
// ---------------------------------------------------------------------------
__global__ __launch_bounds__(256) void split_bf16(const float* __restrict__ x,
                                                  __nv_bfloat16* __restrict__ hi,
                                                  __nv_bfloat16* __restrict__ lo,
                                                  int n4)
{
    int i = blockIdx.x * 256 + threadIdx.x;
    if (i >= n4) return;
    float4 v = ((const float4*)x)[i];
    uint2 H, L;
    split4(v, H, L);
    ((uint2*)hi)[i] = H;
    ((uint2*)lo)[i] = L;
}

// ---------------------------------------------------------------------------
// bf16x3 GEMM via mma.sync — 512 threads, 16 warps (4x4), 32x32 per warp.
// Tests whether 4 warps/SMSP beats 2 (per-warp MMA in-flight limit).
// ---------------------------------------------------------------------------
#define GBM 128
#define GBN 128
#define GBK 32
#define ROWB 80
#define TILE_B (128 * ROWB)
#define STAGE_B (4 * TILE_B)
#define NSTG 3
#define GEMM_SMEM (NSTG * STAGE_B)

__global__ __launch_bounds__(512, 1) void gemm_mma(
    const __nv_bfloat16* __restrict__ Ahi, const __nv_bfloat16* __restrict__ Alo,
    const __nv_bfloat16* __restrict__ Bhi, const __nv_bfloat16* __restrict__ Blo,
    const float* __restrict__ bias, float* __restrict__ C,
    int M, int N, int K)
{
    extern __shared__ char smem[];
    const uint32_t sb = smem_u32(smem);
    const int tid = threadIdx.x, wid = tid >> 5, lane = tid & 31;
    const int warp_m = wid & 3;          // 4 warps over M (32 rows each)
    const int warp_n = wid >> 2;         // 4 warps over N (32 cols each)
    const int bm = blockIdx.x * GBM, bn = blockIdx.y * GBN;

    float acc[2][4][4];
#pragma unroll
    for (int i = 0; i < 2; i++)
#pragma unroll
        for (int j = 0; j < 4; j++)
#pragma unroll
            for (int q = 0; q < 4; q++) acc[i][j][q] = 0.0f;

    // stage loader: 2048 16B chunks, 4 per thread
    auto load_stage = [&](int stg, int k0) {
        uint32_t base = sb + stg * STAGE_B;
#pragma unroll
        for (int i = 0; i < 4; i++) {
            int c = tid + i * 512;
            int tile = c >> 9;          // 0:Ahi 1:Alo 2:Bhi 3:Blo
            int idx = c & 511;
            int row = idx >> 2, ch = idx & 3;
            const __nv_bfloat16* g;
            int grow;
            if (tile < 2) { g = tile ? Alo : Ahi; grow = bm + row; }
            else          { g = (tile == 3) ? Blo : Bhi; grow = bn + row; }
            const char* src = (const char*)(g + (size_t)grow * K + k0) + ch * 16;
            uint32_t dst = base + tile * TILE_B + row * ROWB + ch * 16;
            asm volatile("cp.async.cg.shared.global [%0], [%1], 16;" :: "r"(dst), "l"(src));
        }
        asm volatile("cp.async.commit_group;" ::: "memory");
    };

    const int NKB = K / GBK;
    load_stage(0, 0);
    load_stage(1, GBK);

    const int a_row = (lane & 15);
    const int a_kh = lane >> 4;
    const int b_nrow = (lane & 7) + ((lane >> 4) & 1) * 8;
    const int b_kh = (lane >> 3) & 1;

    for (int kb = 0; kb < NKB; kb++) {
        const int cur = kb % NSTG;
        if (kb + 1 < NKB) { asm volatile("cp.async.wait_group 1;" ::: "memory"); }
        else              { asm volatile("cp.async.wait_group 0;" ::: "memory"); }
        __syncthreads();

        if (kb + 2 < NKB) load_stage((kb + 2) % NSTG, (kb + 2) * GBK);

        const uint32_t stage = sb + cur * STAGE_B;
        const uint32_t Ah = stage;
        const uint32_t Al = stage + TILE_B;
        const uint32_t Bh = stage + 2 * TILE_B;
        const uint32_t Bl = stage + 3 * TILE_B;

#pragma unroll
        for (int ks = 0; ks < 2; ks++) {
            uint32_t ah[2][4], al[2][4];
#pragma unroll
            for (int mf = 0; mf < 2; mf++) {
                uint32_t off = (warp_m * 32 + mf * 16 + a_row) * ROWB + ks * 32 + a_kh * 16;
                ldm_x4(ah[mf], Ah + off);
                ldm_x4(al[mf], Al + off);
            }
            uint32_t bh[2][4], bl[2][4];
#pragma unroll
            for (int p = 0; p < 2; p++) {
                uint32_t off = (warp_n * 32 + p * 16 + b_nrow) * ROWB + ks * 32 + b_kh * 16;
                ldm_x4(bh[p], Bh + off);
                ldm_x4(bl[p], Bl + off);
            }
#pragma unroll
            for (int mf = 0; mf < 2; mf++)
#pragma unroll
                for (int nf = 0; nf < 4; nf++) {
                    const int p = nf >> 1, o = (nf & 1) * 2;
                    mma16816(acc[mf][nf], ah[mf], bh[p][o], bh[p][o + 1]);  // hi*hi
                }
#pragma unroll
            for (int mf = 0; mf < 2; mf++)
#pragma unroll
                for (int nf = 0; nf < 4; nf++) {
                    const int p = nf >> 1, o = (nf & 1) * 2;
                    mma16816(acc[mf][nf], ah[mf], bl[p][o], bl[p][o + 1]);  // hi*lo
                }
#pragma unroll
            for (int mf = 0; mf < 2; mf++)
#pragma unroll
                for (int nf = 0; nf < 4; nf++) {
                    const int p = nf >> 1, o = (nf & 1) * 2;
                    mma16816(acc[mf][nf], al[mf], bh[p][o], bh[p][o + 1]);  // lo*hi
                }
        }
    }

    const int qr = lane >> 2, qc = (lane & 3) * 2;
#pragma unroll
    for (int mf = 0; mf < 2; mf++) {
        int row0 = bm + warp_m * 32 + mf * 16 + qr;
#pragma unroll
        for (int nf = 0; nf < 4; nf++) {
            int col = bn + warp_n * 32 + nf * 8 + qc;
            float2 bv = *(const float2*)(bias + col);
            float2 v0 = { acc[mf][nf][0] + bv.x, acc[mf][nf][1] + bv.y };
            float2 v1 = { acc[mf][nf][2] + bv.x, acc[mf][nf][3] + bv.y };
            *(float2*)(C + (size_t)row0 * N + col) = v0;
            *(float2*)(C + (size_t)(row0 + 8) * N + col) = v1;
        }
    }
}

// ---------------------------------------------------------------------------
// NeoX RoPE (4 heads per 256-thread block)
// ---------------------------------------------------------------------------
__global__ __launch_bounds__(256) void rope_kernel(float* __restrict__ qkv,
                                                   const int* __restrict__ positions)
{
    const int tid = threadIdx.x;
    const int d = tid & 63;
    const int hh = blockIdx.x * 4 + (tid >> 6);
    const int t = blockIdx.y;

    float* base;
    if (hh < NH) base = qkv + (size_t)t * QKVD + hh * HD;
    else         base = qkv + (size_t)t * QKVD + NH * HD + (hh - NH) * HD;

    const float pos = (float)positions[t];
    const float inv_freq = expf(-11.512925464970229f * ((float)d / 64.0f));
    const float ang = pos * inv_freq;
    float s, c;
    sincosf(ang, &s, &c);

    const float x1 = base[d];
    const float x2 = base[d + 64];
    base[d]      = x1 * c - x2 * s;
    base[d + 64] = x2 * c + x1 * s;
}

// ---------------------------------------------------------------------------
// Windowed causal flash attention on HMMA (bf16x3) — round-6 proven.
// ---------------------------------------------------------------------------
#define AROWB 272
#define AQ_B (128 * AROWB)
#define AK_B (64 * AROWB)
#define ATTN_SMEM (AQ_B * 2 + AK_B * 4)

__global__ __launch_bounds__(256, 1) void attn_mma(
    const float* __restrict__ qkv,
    __nv_bfloat16* __restrict__ outHi,
    __nv_bfloat16* __restrict__ outLo,
    const int* __restrict__ winp)
{
    extern __shared__ char smem[];
    const uint32_t sb = smem_u32(smem);
    const uint32_t Qhi = sb,                Qlo = sb + AQ_B;
    const uint32_t Khi = sb + 2 * AQ_B,     Klo = Khi + AK_B;
    const uint32_t Vhi = Klo + AK_B,        Vlo = Vhi + AK_B;

    const int tid = threadIdx.x, w = tid >> 5, lane = tid & 31;
    const int h = blockIdx.y, qt0 = blockIdx.x * 128;
    const int kvh = h / GROUP;
    const int window = *winp;
    const int g = lane >> 2, qc2 = (lane & 3) * 2;

    const size_t qOff = (size_t)h * HD;
    const size_t kOff = (size_t)NH * HD + (size_t)kvh * HD;
    const size_t vOff = kOff + (size_t)NKV * HD;

    for (int idx = tid; idx < 128 * 32; idx += 256) {
        int row = idx >> 5, c4 = idx & 31;
        float4 v = *(const float4*)(qkv + (size_t)(qt0 + row) * QKVD + qOff + c4 * 4);
        uint2 H, L;
        split4(v, H, L);
        *(uint2*)(smem + (Qhi - sb) + row * AROWB + c4 * 8) = H;
        *(uint2*)(smem + (Qlo - sb) + row * AROWB + c4 * 8) = L;
    }

    float m0 = -1e30f, m1 = -1e30f, l0 = 0.0f, l1 = 0.0f;
    float O[16][4];
#pragma unroll
    for (int i = 0; i < 16; i++)
#pragma unroll
        for (int j = 0; j < 4; j++) O[i][j] = 0.0f;

    const int a_row = (lane & 15);
    const int a_kh = lane >> 4;
    const int b_nrow = (lane & 7) + ((lane >> 4) & 1) * 8;
    const int b_kh = (lane >> 3) & 1;
    const int vkr = (lane & 7) + ((lane >> 3) & 1) * 8;
    const int vnc = ((lane >> 4) & 1) * 8;

    const float sc = ATT_SCALE * LOG2E;
    const int qrow0 = qt0 + w * 16 + g;
    const int qrow1 = qrow0 + 8;

    int sBegin = qt0 - window + 1;
    if (sBegin < 0) sBegin = 0;
    sBegin &= ~63;
    const int sEnd = qt0 + 127;

    for (int s0 = sBegin; s0 <= sEnd; s0 += 64) {
        __syncthreads();
        for (int idx = tid; idx < 64 * 32; idx += 256) {
            int row = idx >> 5, c4 = idx & 31;
            float4 kv = *(const float4*)(qkv + (size_t)(s0 + row) * QKVD + kOff + c4 * 4);
            uint2 H, L;
            split4(kv, H, L);
            *(uint2*)(smem + (Khi - sb) + row * AROWB + c4 * 8) = H;
            *(uint2*)(smem + (Klo - sb) + row * AROWB + c4 * 8) = L;
            float4 vv = *(const float4*)(qkv + (size_t)(s0 + row) * QKVD + vOff + c4 * 4);
            split4(vv, H, L);
            *(uint2*)(smem + (Vhi - sb) + row * AROWB + c4 * 8) = H;
            *(uint2*)(smem + (Vlo - sb) + row * AROWB + c4 * 8) = L;
        }
        __syncthreads();

        float S[8][4];
#pragma unroll
        for (int i = 0; i < 8; i++)
#pragma unroll
            for (int j = 0; j < 4; j++) S[i][j] = 0.0f;

#pragma unroll
        for (int kf = 0; kf < 8; kf++) {
            uint32_t ah[4], al[4];
            uint32_t aoff = (w * 16 + a_row) * AROWB + kf * 32 + a_kh * 16;
            ldm_x4(ah, Qhi + aoff);
            ldm_x4(al, Qlo + aoff);
#pragma unroll
            for (int nt = 0; nt < 4; nt++) {
                uint32_t bh[4], bl[4];
                uint32_t boff = (nt * 16 + b_nrow) * AROWB + kf * 32 + b_kh * 16;
                ldm_x4(bh, Khi + boff);
                ldm_x4(bl, Klo + boff);
                mma16816(S[2 * nt],     ah, bh[0], bh[1]);
                mma16816(S[2 * nt + 1], ah, bh[2], bh[3]);
                mma16816(S[2 * nt],     ah, bl[0], bl[1]);
                mma16816(S[2 * nt + 1], ah, bl[2], bl[3]);
                mma16816(S[2 * nt],     al, bh[0], bh[1]);
                mma16816(S[2 * nt + 1], al, bh[2], bh[3]);
            }
        }

#pragma unroll
        for (int nf = 0; nf < 8; nf++) {
            int c0 = s0 + nf * 8 + qc2;
#pragma unroll
            for (int c = 0; c < 4; c++) {
                int col = c0 + (c & 1);
                int row = (c < 2) ? qrow0 : qrow1;
                bool ok = (col <= row) && (col > row - window);
                S[nf][c] = ok ? S[nf][c] * sc : -1e30f;
            }
        }

        float mx0 = -1e30f, mx1 = -1e30f;
#pragma unroll
        for (int nf = 0; nf < 8; nf++) {
            mx0 = fmaxf(mx0, fmaxf(S[nf][0], S[nf][1]));
            mx1 = fmaxf(mx1, fmaxf(S[nf][2], S[nf][3]));
        }
        mx0 = fmaxf(mx0, __shfl_xor_sync(0xffffffffu, mx0, 1));
        mx0 = fmaxf(mx0, __shfl_xor_sync(0xffffffffu, mx0, 2));
        mx1 = fmaxf(mx1, __shfl_xor_sync(0xffffffffu, mx1, 1));
        mx1 = fmaxf(mx1, __shfl_xor_sync(0xffffffffu, mx1, 2));

        float mn0 = fmaxf(m0, mx0), mn1 = fmaxf(m1, mx1);
        float corr0 = exp2f(m0 - mn0), corr1 = exp2f(m1 - mn1);
        m0 = mn0; m1 = mn1;

        uint32_t Phi[4][4], Plo[4][4];
        float rs0 = 0.0f, rs1 = 0.0f;
#pragma unroll
        for (int nf = 0; nf < 8; nf++) {
            float p0 = exp2f(S[nf][0] - mn0);
            float p1 = exp2f(S[nf][1] - mn0);
            float p2 = exp2f(S[nf][2] - mn1);
            float p3 = exp2f(S[nf][3] - mn1);
            rs0 += p0 + p1;
            rs1 += p2 + p3;
            __nv_bfloat16 h0 = __float2bfloat16(p0), h1 = __float2bfloat16(p1);
            __nv_bfloat16 h2 = __float2bfloat16(p2), h3 = __float2bfloat16(p3);
            __nv_bfloat16 e0 = __float2bfloat16(p0 - __bfloat162float(h0));
            __nv_bfloat16 e1 = __float2bfloat16(p1 - __bfloat162float(h1));
            __nv_bfloat16 e2 = __float2bfloat16(p2 - __bfloat162float(h2));
            __nv_bfloat16 e3 = __float2bfloat16(p3 - __bfloat162float(h3));
            const int kf = nf >> 1;
            if ((nf & 1) == 0) {
                Phi[kf][0] = pack2(h0, h1); Phi[kf][1] = pack2(h2, h3);
                Plo[kf][0] = pack2(e0, e1); Plo[kf][1] = pack2(e2, e3);
            } else {
                Phi[kf][2] = pack2(h0, h1); Phi[kf][3] = pack2(h2, h3);
                Plo[kf][2] = pack2(e0, e1); Plo[kf][3] = pack2(e2, e3);
            }
        }
        rs0 += __shfl_xor_sync(0xffffffffu, rs0, 1);
        rs0 += __shfl_xor_sync(0xffffffffu, rs0, 2);
        rs1 += __shfl_xor_sync(0xffffffffu, rs1, 1);
        rs1 += __shfl_xor_sync(0xffffffffu, rs1, 2);

        l0 = l0 * corr0 + rs0;
        l1 = l1 * corr1 + rs1;
#pragma unroll
        for (int nf = 0; nf < 16; nf++) {
            O[nf][0] *= corr0; O[nf][1] *= corr0;
            O[nf][2] *= corr1; O[nf][3] *= corr1;
        }

#pragma unroll
        for (int kf = 0; kf < 4; kf++) {
#pragma unroll
            for (int nt = 0; nt < 8; nt++) {
                uint32_t vh[4], vl[4];
                uint32_t voff = (kf * 16 + vkr) * AROWB + (nt * 16 + vnc) * 2;
                ldm_x4_t(vh, Vhi + voff);
                ldm_x4_t(vl, Vlo + voff);
                mma16816(O[2 * nt],     Phi[kf], vh[0], vh[1]);
                mma16816(O[2 * nt + 1], Phi[kf], vh[2], vh[3]);
                mma16816(O[2 * nt],     Phi[kf], vl[0], vl[1]);
                mma16816(O[2 * nt + 1], Phi[kf], vl[2], vl[3]);
                mma16816(O[2 * nt],     Plo[kf], vh[0], vh[1]);
                mma16816(O[2 * nt + 1], Plo[kf], vh[2], vh[3]);
            }
        }
    }

    const float inv0 = 1.0f / l0, inv1 = 1.0f / l1;
#pragma unroll
    for (int nf = 0; nf < 16; nf++) {
        int col = nf * 8 + qc2;
        size_t base0 = (size_t)qrow0 * HID + h * HD + col;
        size_t base1 = (size_t)qrow1 * HID + h * HD + col;
        float x0 = O[nf][0] * inv0, x1 = O[nf][1] * inv0;
        float x2 = O[nf][2] * inv1, x3 = O[nf][3] * inv1;
        __nv_bfloat16 h0 = __float2bfloat16(x0), h1 = __float2bfloat16(x1);
        __nv_bfloat16 h2 = __float2bfloat16(x2), h3 = __float2bfloat16(x3);
        *(uint32_t*)(outHi + base0) = pack2(h0, h1);
        *(uint32_t*)(outHi + base1) = pack2(h2, h3);
        __nv_bfloat16 e0 = __float2bfloat16(x0 - __bfloat162float(h0));
        __nv_bfloat16 e1 = __float2bfloat16(x1 - __bfloat162float(h1));
        __nv_bfloat16 e2 = __float2bfloat16(x2 - __bfloat162float(h2));
        __nv_bfloat16 e3 = __float2bfloat16(x3 - __bfloat162float(h3));
        *(uint32_t*)(outLo + base0) = pack2(e0, e1);
        *(uint32_t*)(outLo + base1) = pack2(e2, e3);
    }
}

// ---------------------------------------------------------------------------
extern "C" void kernel_launch(void* const* d_in, const int* in_sizes, int n_in,
                              void* d_out, int out_size)
{
    const int*   positions = (const int*)d_in[0];
    const float* hidden    = (const float*)d_in[1];
    const float* wqkv      = (const float*)d_in[2];
    const float* bqkv      = (const float*)d_in[3];
    const float* wo        = (const float*)d_in[4];
    const float* bo        = (const float*)d_in[5];
    const int*   window    = (const int*)d_in[6];
    float* out = (float*)d_out;

    float* qkv_ptr;
    __nv_bfloat16 *hid_hi, *hid_lo, *wqkv_hi, *wqkv_lo, *wo_hi, *wo_lo, *attn_hi, *attn_lo;
    cudaGetSymbolAddress((void**)&qkv_ptr,  g_qkv);
    cudaGetSymbolAddress((void**)&hid_hi,   g_hid_hi);
    cudaGetSymbolAddress((void**)&hid_lo,   g_hid_lo);
    cudaGetSymbolAddress((void**)&wqkv_hi,  g_wqkv_hi);
    cudaGetSymbolAddress((void**)&wqkv_lo,  g_wqkv_lo);
    cudaGetSymbolAddress((void**)&wo_hi,    g_wo_hi);
    cudaGetSymbolAddress((void**)&wo_lo,    g_wo_lo);
    cudaGetSymbolAddress((void**)&attn_hi,  g_attn_hi);
    cudaGetSymbolAddress((void**)&attn_lo,  g_attn_lo);

    cudaFuncSetAttribute(gemm_mma, cudaFuncAttributeMaxDynamicSharedMemorySize, GEMM_SMEM);
    cudaFuncSetAttribute(attn_mma, cudaFuncAttributeMaxDynamicSharedMemorySize, ATTN_SMEM);

    const int nHid  = TT * HID;
    const int nWqkv = QKVD * HID;
    const int nWo   = HID * HID;

    split_bf16<<<(nHid / 4 + 255) / 256, 256>>>(hidden, hid_hi, hid_lo, nHid / 4);
    split_bf16<<<(nWqkv / 4 + 255) / 256, 256>>>(wqkv, wqkv_hi, wqkv_lo, nWqkv / 4);

    gemm_mma<<<dim3(TT / GBM, QKVD / GBN), 512, GEMM_SMEM>>>(
        hid_hi, hid_lo, wqkv_hi, wqkv_lo, bqkv, qkv_ptr, TT, QKVD, HID);

    rope_kernel<<<dim3(10, TT), 256>>>(qkv_ptr, positions);

    attn_mma<<<dim3(TT / 128, NH), 256, ATTN_SMEM>>>(qkv_ptr, attn_hi, attn_lo, window);

    split_bf16<<<(nWo / 4 + 255) / 256, 256>>>(wo, wo_hi, wo_lo, nWo / 4);

    gemm_mma<<<dim3(TT / GBM, HID / GBN), 512, GEMM_SMEM>>>(
        attn_hi, attn_lo, wo_hi, wo_lo, bo, out, TT, HID, HID);
}

// round 9
// speedup vs baseline: 3.0961x; 1.1969x over previous
#include <cuda_runtime.h>
#include <cuda_bf16.h>
#include <cuda_fp16.h>
#include <math.h>
#include <stdint.h>

#define TT 2048
#define HID 4608
#define NH 36
#define NKV 4
#define HD 128
#define QKVD 5632
#define GROUP 9
#define ATT_SCALE 0.08838834764831843f
#define LOG2E 1.4426950408889634f

// ---------------- scratch ----------------
__device__ float g_qkv[TT * QKVD];
__device__ __half g_hid_hi[TT * HID];
__device__ __half g_hid_lo[TT * HID];
__device__ __half g_wqkv_h[QKVD * HID];
__device__ __half g_wo_h[HID * HID];
__device__ __half g_attn_hi[TT * HID];
__device__ __half g_attn_lo[TT * HID];

__device__ __forceinline__ uint32_t smem_u32(const void* p) {
    uint32_t a;
    asm("{ .reg .u64 t; cvta.to.shared.u64 t, %1; cvt.u32.u64 %0, t; }" : "=r"(a) : "l"(p));
    return a;
}
__device__ __forceinline__ void ldm_x4(uint32_t* r, uint32_t addr) {
    asm volatile("ldmatrix.sync.aligned.m8n8.x4.shared.b16 {%0,%1,%2,%3}, [%4];"
                 : "=r"(r[0]), "=r"(r[1]), "=r"(r[2]), "=r"(r[3]) : "r"(addr));
}
__device__ __forceinline__ void ldm_x4_t(uint32_t* r, uint32_t addr) {
    asm volatile("ldmatrix.sync.aligned.m8n8.x4.trans.shared.b16 {%0,%1,%2,%3}, [%4];"
                 : "=r"(r[0]), "=r"(r[1]), "=r"(r[2]), "=r"(r[3]) : "r"(addr));
}
// bf16 MMA (attention)
__device__ __forceinline__ void mma16816(float* d, const uint32_t* a, uint32_t b0, uint32_t b1) {
    asm volatile(
        "mma.sync.aligned.m16n8k16.row.col.f32.bf16.bf16.f32 "
        "{%0,%1,%2,%3}, {%4,%5,%6,%7}, {%8,%9}, {%0,%1,%2,%3};"
        : "+f"(d[0]), "+f"(d[1]), "+f"(d[2]), "+f"(d[3])
        : "r"(a[0]), "r"(a[1]), "r"(a[2]), "r"(a[3]), "r"(b0), "r"(b1));
}
// fp16 MMA (GEMMs)
__device__ __forceinline__ void mma16816h(float* d, const uint32_t* a, uint32_t b0, uint32_t b1) {
    asm volatile(
        "mma.sync.aligned.m16n8k16.row.col.f32.f16.f16.f32 "
        "{%0,%1,%2,%3}, {%4,%5,%6,%7}, {%8,%9}, {%0,%1,%2,%3};"
        : "+f"(d[0]), "+f"(d[1]), "+f"(d[2]), "+f"(d[3])
        : "r"(a[0]), "r"(a[1]), "r"(a[2]), "r"(a[3]), "r"(b0), "r"(b1));
}
__device__ __forceinline__ uint32_t pack2(__nv_bfloat16 a, __nv_bfloat16 b) {
    __nv_bfloat162 t(a, b);
    return *reinterpret_cast<uint32_t*>(&t);
}
__device__ __forceinline__ uint32_t pack2h(__half a, __half b) {
    __half2 t(a, b);
    return *reinterpret_cast<uint32_t*>(&t);
}
__device__ __forceinline__ void split4(float4 v, uint2& hi, uint2& lo) {
    __nv_bfloat16 h0 = __float2bfloat16(v.x), h1 = __float2bfloat16(v.y);
    __nv_bfloat16 h2 = __float2bfloat16(v.z), h3 = __float2bfloat16(v.w);
    __nv_bfloat16 l0 = __float2bfloat16(v.x - __bfloat162float(h0));
    __nv_bfloat16 l1 = __float2bfloat16(v.y - __bfloat162float(h1));
    __nv_bfloat16 l2 = __float2bfloat16(v.z - __bfloat162float(h2));
    __nv_bfloat16 l3 = __float2bfloat16(v.w - __bfloat162float(h3));
    hi.x = pack2(h0, h1); hi.y = pack2(h2, h3);
    lo.x = pack2(l0, l1); lo.y = pack2(l2, l3);
}
__device__ __forceinline__ void split4h(float4 v, uint2& hi, uint2& lo) {
    __half h0 = __float2half(v.x), h1 = __float2half(v.y);
    __half h2 = __float2half(v.z), h3 = __float2half(v.w);
    __half l0 = __float2half(v.x - __half2float(h0));
    __half l1 = __float2half(v.y - __half2float(h1));
    __half l2 = __float2half(v.z - __half2float(h2));
    __half l3 = __float2half(v.w - __half2float(h3));
    hi.x = pack2h(h0, h1); hi.y = pack2h(h2, h3);
    lo.x = pack2h(l0, l1); lo.y = pack2h(l2, l3);
}

// ---------------------------------------------------------------------------
// fp32 -> fp16 hi/lo split (activations)
// ---------------------------------------------------------------------------
__global__ __launch_bounds__(256) void split_f16(const float* __restrict__ x,
                                                 __half* __restrict__ hi,
                                                 __half* __restrict__ lo,
                                                 int n4)
{
    int i = blockIdx.x * 256 + threadIdx.x;
    if (i >= n4) return;
    float4 v = ((const float4*)x)[i];
    uint2 H, L;
    split4h(v, H, L);
    ((uint2*)hi)[i] = H;
    ((uint2*)lo)[i] = L;
}

// fp32 -> fp16 plain convert (weights; no lo needed)
__global__ __launch_bounds__(256) void conv_f16(const float* __restrict__ x,
                                                __half* __restrict__ y,
                                                int n4)
{
    int i = blockIdx.x * 256 + threadIdx.x;
    if (i >= n4) return;
    float4 v = ((const float4*)x)[i];
    uint2 H;
    H.x = pack2h(__float2half(v.x), __float2half(v.y));
    H.y = pack2h(__float2half(v.z), __float2half(v.w));
    ((uint2*)y)[i] = H;
}

// ---------------------------------------------------------------------------
// fp16x2 GEMM: C = A @ B^T + bias, A split hi/lo fp16, B single fp16.
// 128x128 CTA tile, BK=32, 512 threads (16 warps, 4x4), 2 MMAs per k16.
// ---------------------------------------------------------------------------
#define GBM 128
#define GBN 128
#define GBK 32
#define ROWB 80
#define TILE_B (128 * ROWB)
#define STAGE_B (3 * TILE_B)        // Ahi, Alo, Bh = 30720
#define NSTG 3
#define GEMM_SMEM (NSTG * STAGE_B)  // 92160

__global__ __launch_bounds__(512, 1) void gemm_f16(
    const __half* __restrict__ Ahi, const __half* __restrict__ Alo,
    const __half* __restrict__ Bh,
    const float* __restrict__ bias, float* __restrict__ C,
    int M, int N, int K)
{
    extern __shared__ char smem[];
    const uint32_t sb = smem_u32(smem);
    const int tid = threadIdx.x, wid = tid >> 5, lane = tid & 31;
    const int warp_m = wid & 3;
    const int warp_n = wid >> 2;
    const int bm = blockIdx.x * GBM, bn = blockIdx.y * GBN;

    float acc[2][4][4];
#pragma unroll
    for (int i = 0; i < 2; i++)
#pragma unroll
        for (int j = 0; j < 4; j++)
#pragma unroll
            for (int q = 0; q < 4; q++) acc[i][j][q] = 0.0f;

    // stage loader: 1536 16B chunks, 3 per thread
    auto load_stage = [&](int stg, int k0) {
        uint32_t base = sb + stg * STAGE_B;
#pragma unroll
        for (int i = 0; i < 3; i++) {
            int c = tid + i * 512;
            int tile = c >> 9;          // 0:Ahi 1:Alo 2:Bh
            int idx = c & 511;
            int row = idx >> 2, ch = idx & 3;
            const __half* g;
            int grow;
            if (tile == 0) { g = Ahi; grow = bm + row; }
            else if (tile == 1) { g = Alo; grow = bm + row; }
            else { g = Bh; grow = bn + row; }
            const char* src = (const char*)(g + (size_t)grow * K + k0) + ch * 16;
            uint32_t dst = base + tile * TILE_B + row * ROWB + ch * 16;
            asm volatile("cp.async.cg.shared.global [%0], [%1], 16;" :: "r"(dst), "l"(src));
        }
        asm volatile("cp.async.commit_group;" ::: "memory");
    };

    const int NKB = K / GBK;
    load_stage(0, 0);
    load_stage(1, GBK);

    const int a_row = (lane & 15);
    const int a_kh = lane >> 4;
    const int b_nrow = (lane & 7) + ((lane >> 4) & 1) * 8;
    const int b_kh = (lane >> 3) & 1;

    for (int kb = 0; kb < NKB; kb++) {
        const int cur = kb % NSTG;
        if (kb + 1 < NKB) { asm volatile("cp.async.wait_group 1;" ::: "memory"); }
        else              { asm volatile("cp.async.wait_group 0;" ::: "memory"); }
        __syncthreads();

        if (kb + 2 < NKB) load_stage((kb + 2) % NSTG, (kb + 2) * GBK);

        const uint32_t stage = sb + cur * STAGE_B;
        const uint32_t Ah = stage;
        const uint32_t Al = stage + TILE_B;
        const uint32_t Bt = stage + 2 * TILE_B;

#pragma unroll
        for (int ks = 0; ks < 2; ks++) {
            uint32_t ah[2][4], al[2][4];
#pragma unroll
            for (int mf = 0; mf < 2; mf++) {
                uint32_t off = (warp_m * 32 + mf * 16 + a_row) * ROWB + ks * 32 + a_kh * 16;
                ldm_x4(ah[mf], Ah + off);
                ldm_x4(al[mf], Al + off);
            }
            uint32_t bh[2][4];
#pragma unroll
            for (int p = 0; p < 2; p++) {
                uint32_t off = (warp_n * 32 + p * 16 + b_nrow) * ROWB + ks * 32 + b_kh * 16;
                ldm_x4(bh[p], Bt + off);
            }
#pragma unroll
            for (int mf = 0; mf < 2; mf++)
#pragma unroll
                for (int nf = 0; nf < 4; nf++) {
                    const int p = nf >> 1, o = (nf & 1) * 2;
                    mma16816h(acc[mf][nf], ah[mf], bh[p][o], bh[p][o + 1]);  // Ah*B
                }
#pragma unroll
            for (int mf = 0; mf < 2; mf++)
#pragma unroll
                for (int nf = 0; nf < 4; nf++) {
                    const int p = nf >> 1, o = (nf & 1) * 2;
                    mma16816h(acc[mf][nf], al[mf], bh[p][o], bh[p][o + 1]);  // Al*B
                }
        }
    }

    const int qr = lane >> 2, qc = (lane & 3) * 2;
#pragma unroll
    for (int mf = 0; mf < 2; mf++) {
        int row0 = bm + warp_m * 32 + mf * 16 + qr;
#pragma unroll
        for (int nf = 0; nf < 4; nf++) {
            int col = bn + warp_n * 32 + nf * 8 + qc;
            float2 bv = *(const float2*)(bias + col);
            float2 v0 = { acc[mf][nf][0] + bv.x, acc[mf][nf][1] + bv.y };
            float2 v1 = { acc[mf][nf][2] + bv.x, acc[mf][nf][3] + bv.y };
            *(float2*)(C + (size_t)row0 * N + col) = v0;
            *(float2*)(C + (size_t)(row0 + 8) * N + col) = v1;
        }
    }
}

// ---------------------------------------------------------------------------
// NeoX RoPE (4 heads per 256-thread block)
// ---------------------------------------------------------------------------
__global__ __launch_bounds__(256) void rope_kernel(float* __restrict__ qkv,
                                                   const int* __restrict__ positions)
{
    const int tid = threadIdx.x;
    const int d = tid & 63;
    const int hh = blockIdx.x * 4 + (tid >> 6);
    const int t = blockIdx.y;

    float* base;
    if (hh < NH) base = qkv + (size_t)t * QKVD + hh * HD;
    else         base = qkv + (size_t)t * QKVD + NH * HD + (hh - NH) * HD;

    const float pos = (float)positions[t];
    const float inv_freq = expf(-11.512925464970229f * ((float)d / 64.0f));
    const float ang = pos * inv_freq;
    float s, c;
    sincosf(ang, &s, &c);

    const float x1 = base[d];
    const float x2 = base[d + 64];
    base[d]      = x1 * c - x2 * s;
    base[d + 64] = x2 * c + x1 * s;
}

// ---------------------------------------------------------------------------
// Windowed causal flash attention on HMMA (bf16x3 internally).
// Epilogue writes fp16 hi/lo for the fp16x2 output GEMM.
// ---------------------------------------------------------------------------
#define AROWB 272
#define AQ_B (128 * AROWB)
#define AK_B (64 * AROWB)
#define ATTN_SMEM (AQ_B * 2 + AK_B * 4)

__global__ __launch_bounds__(256, 1) void attn_mma(
    const float* __restrict__ qkv,
    __half* __restrict__ outHi,
    __half* __restrict__ outLo,
    const int* __restrict__ winp)
{
    extern __shared__ char smem[];
    const uint32_t sb = smem_u32(smem);
    const uint32_t Qhi = sb,                Qlo = sb + AQ_B;
    const uint32_t Khi = sb + 2 * AQ_B,     Klo = Khi + AK_B;
    const uint32_t Vhi = Klo + AK_B,        Vlo = Vhi + AK_B;

    const int tid = threadIdx.x, w = tid >> 5, lane = tid & 31;
    const int h = blockIdx.y, qt0 = blockIdx.x * 128;
    const int kvh = h / GROUP;
    const int window = *winp;
    const int g = lane >> 2, qc2 = (lane & 3) * 2;

    const size_t qOff = (size_t)h * HD;
    const size_t kOff = (size_t)NH * HD + (size_t)kvh * HD;
    const size_t vOff = kOff + (size_t)NKV * HD;

    for (int idx = tid; idx < 128 * 32; idx += 256) {
        int row = idx >> 5, c4 = idx & 31;
        float4 v = *(const float4*)(qkv + (size_t)(qt0 + row) * QKVD + qOff + c4 * 4);
        uint2 H, L;
        split4(v, H, L);
        *(uint2*)(smem + (Qhi - sb) + row * AROWB + c4 * 8) = H;
        *(uint2*)(smem + (Qlo - sb) + row * AROWB + c4 * 8) = L;
    }

    float m0 = -1e30f, m1 = -1e30f, l0 = 0.0f, l1 = 0.0f;
    float O[16][4];
#pragma unroll
    for (int i = 0; i < 16; i++)
#pragma unroll
        for (int j = 0; j < 4; j++) O[i][j] = 0.0f;

    const int a_row = (lane & 15);
    const int a_kh = lane >> 4;
    const int b_nrow = (lane & 7) + ((lane >> 4) & 1) * 8;
    const int b_kh = (lane >> 3) & 1;
    const int vkr = (lane & 7) + ((lane >> 3) & 1) * 8;
    const int vnc = ((lane >> 4) & 1) * 8;

    const float sc = ATT_SCALE * LOG2E;
    const int qrow0 = qt0 + w * 16 + g;
    const int qrow1 = qrow0 + 8;

    int sBegin = qt0 - window + 1;
    if (sBegin < 0) sBegin = 0;
    sBegin &= ~63;
    const int sEnd = qt0 + 127;

    for (int s0 = sBegin; s0 <= sEnd; s0 += 64) {
        __syncthreads();
        for (int idx = tid; idx < 64 * 32; idx += 256) {
            int row = idx >> 5, c4 = idx & 31;
            float4 kv = *(const float4*)(qkv + (size_t)(s0 + row) * QKVD + kOff + c4 * 4);
            uint2 H, L;
            split4(kv, H, L);
            *(uint2*)(smem + (Khi - sb) + row * AROWB + c4 * 8) = H;
            *(uint2*)(smem + (Klo - sb) + row * AROWB + c4 * 8) = L;
            float4 vv = *(const float4*)(qkv + (size_t)(s0 + row) * QKVD + vOff + c4 * 4);
            split4(vv, H, L);
            *(uint2*)(smem + (Vhi - sb) + row * AROWB + c4 * 8) = H;
            *(uint2*)(smem + (Vlo - sb) + row * AROWB + c4 * 8) = L;
        }
        __syncthreads();

        float S[8][4];
#pragma unroll
        for (int i = 0; i < 8; i++)
#pragma unroll
            for (int j = 0; j < 4; j++) S[i][j] = 0.0f;

#pragma unroll
        for (int kf = 0; kf < 8; kf++) {
            uint32_t ah[4], al[4];
            uint32_t aoff = (w * 16 + a_row) * AROWB + kf * 32 + a_kh * 16;
            ldm_x4(ah, Qhi + aoff);
            ldm_x4(al, Qlo + aoff);
#pragma unroll
            for (int nt = 0; nt < 4; nt++) {
                uint32_t bh[4], bl[4];
                uint32_t boff = (nt * 16 + b_nrow) * AROWB + kf * 32 + b_kh * 16;
                ldm_x4(bh, Khi + boff);
                ldm_x4(bl, Klo + boff);
                mma16816(S[2 * nt],     ah, bh[0], bh[1]);
                mma16816(S[2 * nt + 1], ah, bh[2], bh[3]);
                mma16816(S[2 * nt],     ah, bl[0], bl[1]);
                mma16816(S[2 * nt + 1], ah, bl[2], bl[3]);
                mma16816(S[2 * nt],     al, bh[0], bh[1]);
                mma16816(S[2 * nt + 1], al, bh[2], bh[3]);
            }
        }

#pragma unroll
        for (int nf = 0; nf < 8; nf++) {
            int c0 = s0 + nf * 8 + qc2;
#pragma unroll
            for (int c = 0; c < 4; c++) {
                int col = c0 + (c & 1);
                int row = (c < 2) ? qrow0 : qrow1;
                bool ok = (col <= row) && (col > row - window);
                S[nf][c] = ok ? S[nf][c] * sc : -1e30f;
            }
        }

        float mx0 = -1e30f, mx1 = -1e30f;
#pragma unroll
        for (int nf = 0; nf < 8; nf++) {
            mx0 = fmaxf(mx0, fmaxf(S[nf][0], S[nf][1]));
            mx1 = fmaxf(mx1, fmaxf(S[nf][2], S[nf][3]));
        }
        mx0 = fmaxf(mx0, __shfl_xor_sync(0xffffffffu, mx0, 1));
        mx0 = fmaxf(mx0, __shfl_xor_sync(0xffffffffu, mx0, 2));
        mx1 = fmaxf(mx1, __shfl_xor_sync(0xffffffffu, mx1, 1));
        mx1 = fmaxf(mx1, __shfl_xor_sync(0xffffffffu, mx1, 2));

        float mn0 = fmaxf(m0, mx0), mn1 = fmaxf(m1, mx1);
        float corr0 = exp2f(m0 - mn0), corr1 = exp2f(m1 - mn1);
        m0 = mn0; m1 = mn1;

        uint32_t Phi[4][4], Plo[4][4];
        float rs0 = 0.0f, rs1 = 0.0f;
#pragma unroll
        for (int nf = 0; nf < 8; nf++) {
            float p0 = exp2f(S[nf][0] - mn0);
            float p1 = exp2f(S[nf][1] - mn0);
            float p2 = exp2f(S[nf][2] - mn1);
            float p3 = exp2f(S[nf][3] - mn1);
            rs0 += p0 + p1;
            rs1 += p2 + p3;
            __nv_bfloat16 h0 = __float2bfloat16(p0), h1 = __float2bfloat16(p1);
            __nv_bfloat16 h2 = __float2bfloat16(p2), h3 = __float2bfloat16(p3);
            __nv_bfloat16 e0 = __float2bfloat16(p0 - __bfloat162float(h0));
            __nv_bfloat16 e1 = __float2bfloat16(p1 - __bfloat162float(h1));
            __nv_bfloat16 e2 = __float2bfloat16(p2 - __bfloat162float(h2));
            __nv_bfloat16 e3 = __float2bfloat16(p3 - __bfloat162float(h3));
            const int kf = nf >> 1;
            if ((nf & 1) == 0) {
                Phi[kf][0] = pack2(h0, h1); Phi[kf][1] = pack2(h2, h3);
                Plo[kf][0] = pack2(e0, e1); Plo[kf][1] = pack2(e2, e3);
            } else {
                Phi[kf][2] = pack2(h0, h1); Phi[kf][3] = pack2(h2, h3);
                Plo[kf][2] = pack2(e0, e1); Plo[kf][3] = pack2(e2, e3);
            }
        }
        rs0 += __shfl_xor_sync(0xffffffffu, rs0, 1);
        rs0 += __shfl_xor_sync(0xffffffffu, rs0, 2);
        rs1 += __shfl_xor_sync(0xffffffffu, rs1, 1);
        rs1 += __shfl_xor_sync(0xffffffffu, rs1, 2);

        l0 = l0 * corr0 + rs0;
        l1 = l1 * corr1 + rs1;
#pragma unroll
        for (int nf = 0; nf < 16; nf++) {
            O[nf][0] *= corr0; O[nf][1] *= corr0;
            O[nf][2] *= corr1; O[nf][3] *= corr1;
        }

#pragma unroll
        for (int kf = 0; kf < 4; kf++) {
#pragma unroll
            for (int nt = 0; nt < 8; nt++) {
                uint32_t vh[4], vl[4];
                uint32_t voff = (kf * 16 + vkr) * AROWB + (nt * 16 + vnc) * 2;
                ldm_x4_t(vh, Vhi + voff);
                ldm_x4_t(vl, Vlo + voff);
                mma16816(O[2 * nt],     Phi[kf], vh[0], vh[1]);
                mma16816(O[2 * nt + 1], Phi[kf], vh[2], vh[3]);
                mma16816(O[2 * nt],     Phi[kf], vl[0], vl[1]);
                mma16816(O[2 * nt + 1], Phi[kf], vl[2], vl[3]);
                mma16816(O[2 * nt],     Plo[kf], vh[0], vh[1]);
                mma16816(O[2 * nt + 1], Plo[kf], vh[2], vh[3]);
            }
        }
    }

    // ---- epilogue: normalize, split to fp16 hi/lo, store ----
    const float inv0 = 1.0f / l0, inv1 = 1.0f / l1;
#pragma unroll
    for (int nf = 0; nf < 16; nf++) {
        int col = nf * 8 + qc2;
        size_t base0 = (size_t)qrow0 * HID + h * HD + col;
        size_t base1 = (size_t)qrow1 * HID + h * HD + col;
        float x0 = O[nf][0] * inv0, x1 = O[nf][1] * inv0;
        float x2 = O[nf][2] * inv1, x3 = O[nf][3] * inv1;
        __half h0 = __float2half(x0), h1 = __float2half(x1);
        __half h2 = __float2half(x2), h3 = __float2half(x3);
        *(uint32_t*)(outHi + base0) = pack2h(h0, h1);
        *(uint32_t*)(outHi + base1) = pack2h(h2, h3);
        __half e0 = __float2half(x0 - __half2float(h0));
        __half e1 = __float2half(x1 - __half2float(h1));
        __half e2 = __float2half(x2 - __half2float(h2));
        __half e3 = __float2half(x3 - __half2float(h3));
        *(uint32_t*)(outLo + base0) = pack2h(e0, e1);
        *(uint32_t*)(outLo + base1) = pack2h(e2, e3);
    }
}

// ---------------------------------------------------------------------------
extern "C" void kernel_launch(void* const* d_in, const int* in_sizes, int n_in,
                              void* d_out, int out_size)
{
    const int*   positions = (const int*)d_in[0];
    const float* hidden    = (const float*)d_in[1];
    const float* wqkv      = (const float*)d_in[2];
    const float* bqkv      = (const float*)d_in[3];
    const float* wo        = (const float*)d_in[4];
    const float* bo        = (const float*)d_in[5];
    const int*   window    = (const int*)d_in[6];
    float* out = (float*)d_out;

    float* qkv_ptr;
    __half *hid_hi, *hid_lo, *wqkv_h, *wo_h, *attn_hi, *attn_lo;
    cudaGetSymbolAddress((void**)&qkv_ptr,  g_qkv);
    cudaGetSymbolAddress((void**)&hid_hi,   g_hid_hi);
    cudaGetSymbolAddress((void**)&hid_lo,   g_hid_lo);
    cudaGetSymbolAddress((void**)&wqkv_h,   g_wqkv_h);
    cudaGetSymbolAddress((void**)&wo_h,     g_wo_h);
    cudaGetSymbolAddress((void**)&attn_hi,  g_attn_hi);
    cudaGetSymbolAddress((void**)&attn_lo,  g_attn_lo);

    cudaFuncSetAttribute(gemm_f16, cudaFuncAttributeMaxDynamicSharedMemorySize, GEMM_SMEM);
    cudaFuncSetAttribute(attn_mma, cudaFuncAttributeMaxDynamicSharedMemorySize, ATTN_SMEM);

    const int nHid  = TT * HID;
    const int nWqkv = QKVD * HID;
    const int nWo   = HID * HID;

    split_f16<<<(nHid / 4 + 255) / 256, 256>>>(hidden, hid_hi, hid_lo, nHid / 4);
    conv_f16<<<(nWqkv / 4 + 255) / 256, 256>>>(wqkv, wqkv_h, nWqkv / 4);

    gemm_f16<<<dim3(TT / GBM, QKVD / GBN), 512, GEMM_SMEM>>>(
        hid_hi, hid_lo, wqkv_h, bqkv, qkv_ptr, TT, QKVD, HID);

    rope_kernel<<<dim3(10, TT), 256>>>(qkv_ptr, positions);

    attn_mma<<<dim3(TT / 128, NH), 256, ATTN_SMEM>>>(qkv_ptr, attn_hi, attn_lo, window);

    conv_f16<<<(nWo / 4 + 255) / 256, 256>>>(wo, wo_h, nWo / 4);

    gemm_f16<<<dim3(TT / GBM, HID / GBN), 512, GEMM_SMEM>>>(
        attn_hi, attn_lo, wo_h, bo, out, TT, HID, HID);
}

// round 10
// speedup vs baseline: 3.6202x; 1.1693x over previous
#include <cuda_runtime.h>
#include <cuda_bf16.h>
#include <cuda_fp16.h>
#include <math.h>
#include <stdint.h>

#define TT 2048
#define HID 4608
#define NH 36
#define NKV 4
#define HD 128
#define QKVD 5632
#define GROUP 9
#define ATT_SCALE 0.08838834764831843f
#define LOG2E 1.4426950408889634f

// ---------------- scratch ----------------
__device__ float g_qkv[TT * QKVD];
__device__ __half g_hid_hi[TT * HID];
__device__ __half g_hid_lo[TT * HID];
__device__ __half g_wqkv_h[QKVD * HID];
__device__ __half g_wo_h[HID * HID];
__device__ __half g_attn_hi[TT * HID];
__device__ __half g_attn_lo[TT * HID];

__device__ __forceinline__ uint32_t smem_u32(const void* p) {
    uint32_t a;
    asm("{ .reg .u64 t; cvta.to.shared.u64 t, %1; cvt.u32.u64 %0, t; }" : "=r"(a) : "l"(p));
    return a;
}
__device__ __forceinline__ void ldm_x4(uint32_t* r, uint32_t addr) {
    asm volatile("ldmatrix.sync.aligned.m8n8.x4.shared.b16 {%0,%1,%2,%3}, [%4];"
                 : "=r"(r[0]), "=r"(r[1]), "=r"(r[2]), "=r"(r[3]) : "r"(addr));
}
__device__ __forceinline__ void ldm_x4_t(uint32_t* r, uint32_t addr) {
    asm volatile("ldmatrix.sync.aligned.m8n8.x4.trans.shared.b16 {%0,%1,%2,%3}, [%4];"
                 : "=r"(r[0]), "=r"(r[1]), "=r"(r[2]), "=r"(r[3]) : "r"(addr));
}
// bf16 MMA (attention)
__device__ __forceinline__ void mma16816(float* d, const uint32_t* a, uint32_t b0, uint32_t b1) {
    asm volatile(
        "mma.sync.aligned.m16n8k16.row.col.f32.bf16.bf16.f32 "
        "{%0,%1,%2,%3}, {%4,%5,%6,%7}, {%8,%9}, {%0,%1,%2,%3};"
        : "+f"(d[0]), "+f"(d[1]), "+f"(d[2]), "+f"(d[3])
        : "r"(a[0]), "r"(a[1]), "r"(a[2]), "r"(a[3]), "r"(b0), "r"(b1));
}
// fp16 MMA (GEMMs)
__device__ __forceinline__ void mma16816h(float* d, const uint32_t* a, uint32_t b0, uint32_t b1) {
    asm volatile(
        "mma.sync.aligned.m16n8k16.row.col.f32.f16.f16.f32 "
        "{%0,%1,%2,%3}, {%4,%5,%6,%7}, {%8,%9}, {%0,%1,%2,%3};"
        : "+f"(d[0]), "+f"(d[1]), "+f"(d[2]), "+f"(d[3])
        : "r"(a[0]), "r"(a[1]), "r"(a[2]), "r"(a[3]), "r"(b0), "r"(b1));
}
__device__ __forceinline__ uint32_t pack2(__nv_bfloat16 a, __nv_bfloat16 b) {
    __nv_bfloat162 t(a, b);
    return *reinterpret_cast<uint32_t*>(&t);
}
__device__ __forceinline__ uint32_t pack2h(__half a, __half b) {
    __half2 t(a, b);
    return *reinterpret_cast<uint32_t*>(&t);
}
__device__ __forceinline__ void split4(float4 v, uint2& hi, uint2& lo) {
    __nv_bfloat16 h0 = __float2bfloat16(v.x), h1 = __float2bfloat16(v.y);
    __nv_bfloat16 h2 = __float2bfloat16(v.z), h3 = __float2bfloat16(v.w);
    __nv_bfloat16 l0 = __float2bfloat16(v.x - __bfloat162float(h0));
    __nv_bfloat16 l1 = __float2bfloat16(v.y - __bfloat162float(h1));
    __nv_bfloat16 l2 = __float2bfloat16(v.z - __bfloat162float(h2));
    __nv_bfloat16 l3 = __float2bfloat16(v.w - __bfloat162float(h3));
    hi.x = pack2(h0, h1); hi.y = pack2(h2, h3);
    lo.x = pack2(l0, l1); lo.y = pack2(l2, l3);
}
__device__ __forceinline__ void split4h(float4 v, uint2& hi, uint2& lo) {
    __half h0 = __float2half(v.x), h1 = __float2half(v.y);
    __half h2 = __float2half(v.z), h3 = __float2half(v.w);
    __half l0 = __float2half(v.x - __half2float(h0));
    __half l1 = __float2half(v.y - __half2float(h1));
    __half l2 = __float2half(v.z - __half2float(h2));
    __half l3 = __float2half(v.w - __half2float(h3));
    hi.x = pack2h(h0, h1); hi.y = pack2h(h2, h3);
    lo.x = pack2h(l0, l1); lo.y = pack2h(l2, l3);
}

// ---------------------------------------------------------------------------
// fp32 -> fp16 hi/lo split (activations)
// ---------------------------------------------------------------------------
__global__ __launch_bounds__(256) void split_f16(const float* __restrict__ x,
                                                 __half* __restrict__ hi,
                                                 __half* __restrict__ lo,
                                                 int n4)
{
    int i = blockIdx.x * 256 + threadIdx.x;
    if (i >= n4) return;
    float4 v = ((const float4*)x)[i];
    uint2 H, L;
    split4h(v, H, L);
    ((uint2*)hi)[i] = H;
    ((uint2*)lo)[i] = L;
}

// fp32 -> fp16 plain convert (weights)
__global__ __launch_bounds__(256) void conv_f16(const float* __restrict__ x,
                                                __half* __restrict__ y,
                                                int n4)
{
    int i = blockIdx.x * 256 + threadIdx.x;
    if (i >= n4) return;
    float4 v = ((const float4*)x)[i];
    uint2 H;
    H.x = pack2h(__float2half(v.x), __float2half(v.y));
    H.y = pack2h(__float2half(v.z), __float2half(v.w));
    ((uint2*)y)[i] = H;
}

// ---------------------------------------------------------------------------
// fp16x2 GEMM: C = A @ B^T + bias, A split hi/lo fp16, B single fp16.
// 128x128 CTA tile, BK=64 (halved K-block overhead), 512 threads (16 warps).
// Rows padded to 144B (144 mod 128 = 16 -> conflict-free ldmatrix).
// ---------------------------------------------------------------------------
#define GBM 128
#define GBN 128
#define GBK 64
#define ROWB 144
#define TILE_B (128 * ROWB)         // 18432
#define STAGE_B (3 * TILE_B)        // Ahi, Alo, Bh = 55296
#define NSTG 3
#define GEMM_SMEM (NSTG * STAGE_B)  // 165888

__global__ __launch_bounds__(512, 1) void gemm_f16(
    const __half* __restrict__ Ahi, const __half* __restrict__ Alo,
    const __half* __restrict__ Bh,
    const float* __restrict__ bias, float* __restrict__ C,
    int M, int N, int K)
{
    extern __shared__ char smem[];
    const uint32_t sb = smem_u32(smem);
    const int tid = threadIdx.x, wid = tid >> 5, lane = tid & 31;
    const int warp_m = wid & 3;
    const int warp_n = wid >> 2;
    const int bm = blockIdx.x * GBM, bn = blockIdx.y * GBN;

    float acc[2][4][4];
#pragma unroll
    for (int i = 0; i < 2; i++)
#pragma unroll
        for (int j = 0; j < 4; j++)
#pragma unroll
            for (int q = 0; q < 4; q++) acc[i][j][q] = 0.0f;

    // stage loader: 3 tiles x 128 rows x 8 chunks(16B) = 3072 chunks, 6/thread
    auto load_stage = [&](int stg, int k0) {
        uint32_t base = sb + stg * STAGE_B;
#pragma unroll
        for (int i = 0; i < 6; i++) {
            int c = tid + i * 512;
            int tile = c >> 10;         // 0:Ahi 1:Alo 2:Bh
            int idx = c & 1023;
            int row = idx >> 3, ch = idx & 7;
            const __half* g;
            int grow;
            if (tile == 0) { g = Ahi; grow = bm + row; }
            else if (tile == 1) { g = Alo; grow = bm + row; }
            else { g = Bh; grow = bn + row; }
            const char* src = (const char*)(g + (size_t)grow * K + k0) + ch * 16;
            uint32_t dst = base + tile * TILE_B + row * ROWB + ch * 16;
            asm volatile("cp.async.cg.shared.global [%0], [%1], 16;" :: "r"(dst), "l"(src));
        }
        asm volatile("cp.async.commit_group;" ::: "memory");
    };

    const int NKB = K / GBK;   // 72
    load_stage(0, 0);
    load_stage(1, GBK);

    const int a_row = (lane & 15);
    const int a_kh = lane >> 4;
    const int b_nrow = (lane & 7) + ((lane >> 4) & 1) * 8;
    const int b_kh = (lane >> 3) & 1;

    for (int kb = 0; kb < NKB; kb++) {
        const int cur = kb % NSTG;
        if (kb + 1 < NKB) { asm volatile("cp.async.wait_group 1;" ::: "memory"); }
        else              { asm volatile("cp.async.wait_group 0;" ::: "memory"); }
        __syncthreads();

        if (kb + 2 < NKB) load_stage((kb + 2) % NSTG, (kb + 2) * GBK);

        const uint32_t stage = sb + cur * STAGE_B;
        const uint32_t Ah = stage;
        const uint32_t Al = stage + TILE_B;
        const uint32_t Bt = stage + 2 * TILE_B;

#pragma unroll
        for (int ks = 0; ks < 4; ks++) {
            uint32_t ah[2][4], al[2][4];
#pragma unroll
            for (int mf = 0; mf < 2; mf++) {
                uint32_t off = (warp_m * 32 + mf * 16 + a_row) * ROWB + ks * 32 + a_kh * 16;
                ldm_x4(ah[mf], Ah + off);
                ldm_x4(al[mf], Al + off);
            }
            uint32_t bh[2][4];
#pragma unroll
            for (int p = 0; p < 2; p++) {
                uint32_t off = (warp_n * 32 + p * 16 + b_nrow) * ROWB + ks * 32 + b_kh * 16;
                ldm_x4(bh[p], Bt + off);
            }
#pragma unroll
            for (int mf = 0; mf < 2; mf++)
#pragma unroll
                for (int nf = 0; nf < 4; nf++) {
                    const int p = nf >> 1, o = (nf & 1) * 2;
                    mma16816h(acc[mf][nf], ah[mf], bh[p][o], bh[p][o + 1]);  // Ah*B
                }
#pragma unroll
            for (int mf = 0; mf < 2; mf++)
#pragma unroll
                for (int nf = 0; nf < 4; nf++) {
                    const int p = nf >> 1, o = (nf & 1) * 2;
                    mma16816h(acc[mf][nf], al[mf], bh[p][o], bh[p][o + 1]);  // Al*B
                }
        }
    }

    const int qr = lane >> 2, qc = (lane & 3) * 2;
#pragma unroll
    for (int mf = 0; mf < 2; mf++) {
        int row0 = bm + warp_m * 32 + mf * 16 + qr;
#pragma unroll
        for (int nf = 0; nf < 4; nf++) {
            int col = bn + warp_n * 32 + nf * 8 + qc;
            float2 bv = *(const float2*)(bias + col);
            float2 v0 = { acc[mf][nf][0] + bv.x, acc[mf][nf][1] + bv.y };
            float2 v1 = { acc[mf][nf][2] + bv.x, acc[mf][nf][3] + bv.y };
            *(float2*)(C + (size_t)row0 * N + col) = v0;
            *(float2*)(C + (size_t)(row0 + 8) * N + col) = v1;
        }
    }
}

// ---------------------------------------------------------------------------
// NeoX RoPE (4 heads per 256-thread block)
// ---------------------------------------------------------------------------
__global__ __launch_bounds__(256) void rope_kernel(float* __restrict__ qkv,
                                                   const int* __restrict__ positions)
{
    const int tid = threadIdx.x;
    const int d = tid & 63;
    const int hh = blockIdx.x * 4 + (tid >> 6);
    const int t = blockIdx.y;

    float* base;
    if (hh < NH) base = qkv + (size_t)t * QKVD + hh * HD;
    else         base = qkv + (size_t)t * QKVD + NH * HD + (hh - NH) * HD;

    const float pos = (float)positions[t];
    const float inv_freq = expf(-11.512925464970229f * ((float)d / 64.0f));
    const float ang = pos * inv_freq;
    float s, c;
    sincosf(ang, &s, &c);

    const float x1 = base[d];
    const float x2 = base[d + 64];
    base[d]      = x1 * c - x2 * s;
    base[d + 64] = x2 * c + x1 * s;
}

// ---------------------------------------------------------------------------
// Windowed causal flash attention on HMMA (bf16x3 internally).
// Epilogue writes fp16 hi/lo for the fp16x2 output GEMM.
// ---------------------------------------------------------------------------
#define AROWB 272
#define AQ_B (128 * AROWB)
#define AK_B (64 * AROWB)
#define ATTN_SMEM (AQ_B * 2 + AK_B * 4)

__global__ __launch_bounds__(256, 1) void attn_mma(
    const float* __restrict__ qkv,
    __half* __restrict__ outHi,
    __half* __restrict__ outLo,
    const int* __restrict__ winp)
{
    extern __shared__ char smem[];
    const uint32_t sb = smem_u32(smem);
    const uint32_t Qhi = sb,                Qlo = sb + AQ_B;
    const uint32_t Khi = sb + 2 * AQ_B,     Klo = Khi + AK_B;
    const uint32_t Vhi = Klo + AK_B,        Vlo = Vhi + AK_B;

    const int tid = threadIdx.x, w = tid >> 5, lane = tid & 31;
    const int h = blockIdx.y, qt0 = blockIdx.x * 128;
    const int kvh = h / GROUP;
    const int window = *winp;
    const int g = lane >> 2, qc2 = (lane & 3) * 2;

    const size_t qOff = (size_t)h * HD;
    const size_t kOff = (size_t)NH * HD + (size_t)kvh * HD;
    const size_t vOff = kOff + (size_t)NKV * HD;

    for (int idx = tid; idx < 128 * 32; idx += 256) {
        int row = idx >> 5, c4 = idx & 31;
        float4 v = *(const float4*)(qkv + (size_t)(qt0 + row) * QKVD + qOff + c4 * 4);
        uint2 H, L;
        split4(v, H, L);
        *(uint2*)(smem + (Qhi - sb) + row * AROWB + c4 * 8) = H;
        *(uint2*)(smem + (Qlo - sb) + row * AROWB + c4 * 8) = L;
    }

    float m0 = -1e30f, m1 = -1e30f, l0 = 0.0f, l1 = 0.0f;
    float O[16][4];
#pragma unroll
    for (int i = 0; i < 16; i++)
#pragma unroll
        for (int j = 0; j < 4; j++) O[i][j] = 0.0f;

    const int a_row = (lane & 15);
    const int a_kh = lane >> 4;
    const int b_nrow = (lane & 7) + ((lane >> 4) & 1) * 8;
    const int b_kh = (lane >> 3) & 1;
    const int vkr = (lane & 7) + ((lane >> 3) & 1) * 8;
    const int vnc = ((lane >> 4) & 1) * 8;

    const float sc = ATT_SCALE * LOG2E;
    const int qrow0 = qt0 + w * 16 + g;
    const int qrow1 = qrow0 + 8;

    int sBegin = qt0 - window + 1;
    if (sBegin < 0) sBegin = 0;
    sBegin &= ~63;
    const int sEnd = qt0 + 127;

    for (int s0 = sBegin; s0 <= sEnd; s0 += 64) {
        __syncthreads();
        for (int idx = tid; idx < 64 * 32; idx += 256) {
            int row = idx >> 5, c4 = idx & 31;
            float4 kv = *(const float4*)(qkv + (size_t)(s0 + row) * QKVD + kOff + c4 * 4);
            uint2 H, L;
            split4(kv, H, L);
            *(uint2*)(smem + (Khi - sb) + row * AROWB + c4 * 8) = H;
            *(uint2*)(smem + (Klo - sb) + row * AROWB + c4 * 8) = L;
            float4 vv = *(const float4*)(qkv + (size_t)(s0 + row) * QKVD + vOff + c4 * 4);
            split4(vv, H, L);
            *(uint2*)(smem + (Vhi - sb) + row * AROWB + c4 * 8) = H;
            *(uint2*)(smem + (Vlo - sb) + row * AROWB + c4 * 8) = L;
        }
        __syncthreads();

        float S[8][4];
#pragma unroll
        for (int i = 0; i < 8; i++)
#pragma unroll
            for (int j = 0; j < 4; j++) S[i][j] = 0.0f;

#pragma unroll
        for (int kf = 0; kf < 8; kf++) {
            uint32_t ah[4], al[4];
            uint32_t aoff = (w * 16 + a_row) * AROWB + kf * 32 + a_kh * 16;
            ldm_x4(ah, Qhi + aoff);
            ldm_x4(al, Qlo + aoff);
#pragma unroll
            for (int nt = 0; nt < 4; nt++) {
                uint32_t bh[4], bl[4];
                uint32_t boff = (nt * 16 + b_nrow) * AROWB + kf * 32 + b_kh * 16;
                ldm_x4(bh, Khi + boff);
                ldm_x4(bl, Klo + boff);
                mma16816(S[2 * nt],     ah, bh[0], bh[1]);
                mma16816(S[2 * nt + 1], ah, bh[2], bh[3]);
                mma16816(S[2 * nt],     ah, bl[0], bl[1]);
                mma16816(S[2 * nt + 1], ah, bl[2], bl[3]);
                mma16816(S[2 * nt],     al, bh[0], bh[1]);
                mma16816(S[2 * nt + 1], al, bh[2], bh[3]);
            }
        }

#pragma unroll
        for (int nf = 0; nf < 8; nf++) {
            int c0 = s0 + nf * 8 + qc2;
#pragma unroll
            for (int c = 0; c < 4; c++) {
                int col = c0 + (c & 1);
                int row = (c < 2) ? qrow0 : qrow1;
                bool ok = (col <= row) && (col > row - window);
                S[nf][c] = ok ? S[nf][c] * sc : -1e30f;
            }
        }

        float mx0 = -1e30f, mx1 = -1e30f;
#pragma unroll
        for (int nf = 0; nf < 8; nf++) {
            mx0 = fmaxf(mx0, fmaxf(S[nf][0], S[nf][1]));
            mx1 = fmaxf(mx1, fmaxf(S[nf][2], S[nf][3]));
        }
        mx0 = fmaxf(mx0, __shfl_xor_sync(0xffffffffu, mx0, 1));
        mx0 = fmaxf(mx0, __shfl_xor_sync(0xffffffffu, mx0, 2));
        mx1 = fmaxf(mx1, __shfl_xor_sync(0xffffffffu, mx1, 1));
        mx1 = fmaxf(mx1, __shfl_xor_sync(0xffffffffu, mx1, 2));

        float mn0 = fmaxf(m0, mx0), mn1 = fmaxf(m1, mx1);
        float corr0 = exp2f(m0 - mn0), corr1 = exp2f(m1 - mn1);
        m0 = mn0; m1 = mn1;

        uint32_t Phi[4][4], Plo[4][4];
        float rs0 = 0.0f, rs1 = 0.0f;
#pragma unroll
        for (int nf = 0; nf < 8; nf++) {
            float p0 = exp2f(S[nf][0] - mn0);
            float p1 = exp2f(S[nf][1] - mn0);
            float p2 = exp2f(S[nf][2] - mn1);
            float p3 = exp2f(S[nf][3] - mn1);
            rs0 += p0 + p1;
            rs1 += p2 + p3;
            __nv_bfloat16 h0 = __float2bfloat16(p0), h1 = __float2bfloat16(p1);
            __nv_bfloat16 h2 = __float2bfloat16(p2), h3 = __float2bfloat16(p3);
            __nv_bfloat16 e0 = __float2bfloat16(p0 - __bfloat162float(h0));
            __nv_bfloat16 e1 = __float2bfloat16(p1 - __bfloat162float(h1));
            __nv_bfloat16 e2 = __float2bfloat16(p2 - __bfloat162float(h2));
            __nv_bfloat16 e3 = __float2bfloat16(p3 - __bfloat162float(h3));
            const int kf = nf >> 1;
            if ((nf & 1) == 0) {
                Phi[kf][0] = pack2(h0, h1); Phi[kf][1] = pack2(h2, h3);
                Plo[kf][0] = pack2(e0, e1); Plo[kf][1] = pack2(e2, e3);
            } else {
                Phi[kf][2] = pack2(h0, h1); Phi[kf][3] = pack2(h2, h3);
                Plo[kf][2] = pack2(e0, e1); Plo[kf][3] = pack2(e2, e3);
            }
        }
        rs0 += __shfl_xor_sync(0xffffffffu, rs0, 1);
        rs0 += __shfl_xor_sync(0xffffffffu, rs0, 2);
        rs1 += __shfl_xor_sync(0xffffffffu, rs1, 1);
        rs1 += __shfl_xor_sync(0xffffffffu, rs1, 2);

        l0 = l0 * corr0 + rs0;
        l1 = l1 * corr1 + rs1;
#pragma unroll
        for (int nf = 0; nf < 16; nf++) {
            O[nf][0] *= corr0; O[nf][1] *= corr0;
            O[nf][2] *= corr1; O[nf][3] *= corr1;
        }

#pragma unroll
        for (int kf = 0; kf < 4; kf++) {
#pragma unroll
            for (int nt = 0; nt < 8; nt++) {
                uint32_t vh[4], vl[4];
                uint32_t voff = (kf * 16 + vkr) * AROWB + (nt * 16 + vnc) * 2;
                ldm_x4_t(vh, Vhi + voff);
                ldm_x4_t(vl, Vlo + voff);
                mma16816(O[2 * nt],     Phi[kf], vh[0], vh[1]);
                mma16816(O[2 * nt + 1], Phi[kf], vh[2], vh[3]);
                mma16816(O[2 * nt],     Phi[kf], vl[0], vl[1]);
                mma16816(O[2 * nt + 1], Phi[kf], vl[2], vl[3]);
                mma16816(O[2 * nt],     Plo[kf], vh[0], vh[1]);
                mma16816(O[2 * nt + 1], Plo[kf], vh[2], vh[3]);
            }
        }
    }

    // ---- epilogue: normalize, split to fp16 hi/lo, store ----
    const float inv0 = 1.0f / l0, inv1 = 1.0f / l1;
#pragma unroll
    for (int nf = 0; nf < 16; nf++) {
        int col = nf * 8 + qc2;
        size_t base0 = (size_t)qrow0 * HID + h * HD + col;
        size_t base1 = (size_t)qrow1 * HID + h * HD + col;
        float x0 = O[nf][0] * inv0, x1 = O[nf][1] * inv0;
        float x2 = O[nf][2] * inv1, x3 = O[nf][3] * inv1;
        __half h0 = __float2half(x0), h1 = __float2half(x1);
        __half h2 = __float2half(x2), h3 = __float2half(x3);
        *(uint32_t*)(outHi + base0) = pack2h(h0, h1);
        *(uint32_t*)(outHi + base1) = pack2h(h2, h3);
        __half e0 = __float2half(x0 - __half2float(h0));
        __half e1 = __float2half(x1 - __half2float(h1));
        __half e2 = __float2half(x2 - __half2float(h2));
        __half e3 = __float2half(x3 - __half2float(h3));
        *(uint32_t*)(outLo + base0) = pack2h(e0, e1);
        *(uint32_t*)(outLo + base1) = pack2h(e2, e3);
    }
}

// ---------------------------------------------------------------------------
extern "C" void kernel_launch(void* const* d_in, const int* in_sizes, int n_in,
                              void* d_out, int out_size)
{
    const int*   positions = (const int*)d_in[0];
    const float* hidden    = (const float*)d_in[1];
    const float* wqkv      = (const float*)d_in[2];
    const float* bqkv      = (const float*)d_in[3];
    const float* wo        = (const float*)d_in[4];
    const float* bo        = (const float*)d_in[5];
    const int*   window    = (const int*)d_in[6];
    float* out = (float*)d_out;

    float* qkv_ptr;
    __half *hid_hi, *hid_lo, *wqkv_h, *wo_h, *attn_hi, *attn_lo;
    cudaGetSymbolAddress((void**)&qkv_ptr,  g_qkv);
    cudaGetSymbolAddress((void**)&hid_hi,   g_hid_hi);
    cudaGetSymbolAddress((void**)&hid_lo,   g_hid_lo);
    cudaGetSymbolAddress((void**)&wqkv_h,   g_wqkv_h);
    cudaGetSymbolAddress((void**)&wo_h,     g_wo_h);
    cudaGetSymbolAddress((void**)&attn_hi,  g_attn_hi);
    cudaGetSymbolAddress((void**)&attn_lo,  g_attn_lo);

    cudaFuncSetAttribute(gemm_f16, cudaFuncAttributeMaxDynamicSharedMemorySize, GEMM_SMEM);
    cudaFuncSetAttribute(attn_mma, cudaFuncAttributeMaxDynamicSharedMemorySize, ATTN_SMEM);

    const int nHid  = TT * HID;
    const int nWqkv = QKVD * HID;
    const int nWo   = HID * HID;

    split_f16<<<(nHid / 4 + 255) / 256, 256>>>(hidden, hid_hi, hid_lo, nHid / 4);
    conv_f16<<<(nWqkv / 4 + 255) / 256, 256>>>(wqkv, wqkv_h, nWqkv / 4);

    gemm_f16<<<dim3(TT / GBM, QKVD / GBN), 512, GEMM_SMEM>>>(
        hid_hi, hid_lo, wqkv_h, bqkv, qkv_ptr, TT, QKVD, HID);

    rope_kernel<<<dim3(10, TT), 256>>>(qkv_ptr, positions);

    attn_mma<<<dim3(TT / 128, NH), 256, ATTN_SMEM>>>(qkv_ptr, attn_hi, attn_lo, window);

    conv_f16<<<(nWo / 4 + 255) / 256, 256>>>(wo, wo_h, nWo / 4);

    gemm_f16<<<dim3(TT / GBM, HID / GBN), 512, GEMM_SMEM>>>(
        attn_hi, attn_lo, wo_h, bo, out, TT, HID, HID);
}